// round 2
// baseline (speedup 1.0000x reference)
#include <cuda_runtime.h>
#include <cstdint>

#define HW 25600
#define P4 102400   // 4 images * HW  (img 0,1 = x_l b0,b1 ; img 2,3 = x_r b0,b1)
#define P2 51200    // 2 batches * HW

// ------------------------- scratch (__device__ globals) -------------------------
__device__ float g_h[(size_t)P4 * 128];     // LN1+pw1 out, NHWC
__device__ float g_v[(size_t)P4 * 128];     // value proj
__device__ float g_dw[(size_t)P4 * 128];    // depthwise conv out
__device__ float g_om[(size_t)P4 * 112];    // offset/mask proj (first 108 used)
__device__ float g_samp[(size_t)P4 * 128];  // deform-sampled features
__device__ float g_f[(size_t)P4 * 64];      // gated branch features
__device__ float g_y[(size_t)P2 * 128];     // [y_l(64) ; y_r(64)] NHWC per batch
__device__ float g_zg[(size_t)P2 * 64];     // gated conv4 output
__device__ float g_part[64 * 64];           // pooling partials [img*16+seg][64]
__device__ float g_s[256];                  // SCA scale s[b][128]

// ------------------------- kernel 1: LN(64ch) + pw1 (64 -> 128) -------------------------
__global__ void __launch_bounds__(256) k_ln_pw1(const float* __restrict__ x_l,
                                                const float* __restrict__ x_r,
                                                const float* __restrict__ g1,
                                                const float* __restrict__ W,
                                                const float* __restrict__ Bb) {
    extern __shared__ float sm[];
    float* Xs = sm;                  // 64 px * 68
    float* Ws = sm + 64 * 68;        // 128*64
    float* mr = Ws + 128 * 64;       // 128
    int tid = threadIdx.x;
    int base = blockIdx.x * 64;
    int img = base / HW;
    int pos = base - img * HW;
    const float* xp = (img < 2) ? (x_l + (size_t)img * HW * 64)
                                : (x_r + (size_t)(img - 2) * HW * 64);
    for (int i = tid; i < 64 * 64; i += 256) {
        int c = i >> 6, p = i & 63;
        Xs[p * 68 + c] = xp[(size_t)c * HW + pos + p];
    }
    for (int i = tid; i < 128 * 64; i += 256) Ws[i] = W[i];
    __syncthreads();
    if (tid < 64) {
        float s = 0.f, sq = 0.f;
        for (int c = 0; c < 64; c++) { float v = Xs[tid * 68 + c]; s += v; sq += v * v; }
        float m = s * (1.f / 64.f);
        float var = sq * (1.f / 64.f) - m * m;
        mr[tid] = m; mr[64 + tid] = rsqrtf(var + 1e-5f);
    }
    __syncthreads();
    for (int i = tid; i < 64 * 64; i += 256) {
        int p = i >> 6, c = i & 63;
        Xs[p * 68 + c] = (Xs[p * 68 + c] - mr[p]) * mr[64 + p] * __ldg(&g1[c]);
    }
    __syncthreads();
    int pr = tid & 15, og = tid >> 4;
    float acc[4][8];
#pragma unroll
    for (int j = 0; j < 8; j++) {
        float b = Bb[og * 8 + j];
#pragma unroll
        for (int i = 0; i < 4; i++) acc[i][j] = b;
    }
#pragma unroll 4
    for (int k = 0; k < 64; k += 4) {
        float4 xv[4];
#pragma unroll
        for (int i = 0; i < 4; i++) xv[i] = *(const float4*)&Xs[(pr + 16 * i) * 68 + k];
#pragma unroll
        for (int j = 0; j < 8; j++) {
            float4 wv = *(const float4*)&Ws[(og * 8 + j) * 64 + k];
#pragma unroll
            for (int i = 0; i < 4; i++)
                acc[i][j] += xv[i].x * wv.x + xv[i].y * wv.y + xv[i].z * wv.z + xv[i].w * wv.w;
        }
    }
#pragma unroll
    for (int i = 0; i < 4; i++)
#pragma unroll
        for (int j = 0; j < 8; j++)
            g_h[(size_t)(base + pr + 16 * i) * 128 + og * 8 + j] = acc[i][j];
}

// ------------------------- generic GEMM body: Y[p,o] = X[p,:]·W[o,:] + B -------------------------
template <int K, int N>
__device__ __forceinline__ void gemm_body(const float* __restrict__ X,
                                          float* __restrict__ Y,
                                          const float* __restrict__ W,
                                          const float* __restrict__ Bb) {
    extern __shared__ float sm[];
    float* Ws = sm;              // N*K
    float* Xs = sm + N * K;      // 64*(K+4)
    int tid = threadIdx.x;
    int base = blockIdx.x * 64;
    for (int i = tid; i < N * K; i += 256) Ws[i] = W[i];
    for (int i = tid; i < 64 * K; i += 256) {
        int p = i / K, k = i - p * K;
        Xs[p * (K + 4) + k] = X[(size_t)(base + p) * K + k];
    }
    __syncthreads();
    constexpr int OPT = N / 16;
    int pr = tid & 15, og = tid >> 4;
    float acc[4][OPT];
#pragma unroll
    for (int j = 0; j < OPT; j++) {
        float b = Bb[og * OPT + j];
#pragma unroll
        for (int i = 0; i < 4; i++) acc[i][j] = b;
    }
#pragma unroll 4
    for (int k = 0; k < K; k += 4) {
        float4 xv[4];
#pragma unroll
        for (int i = 0; i < 4; i++) xv[i] = *(const float4*)&Xs[(pr + 16 * i) * (K + 4) + k];
#pragma unroll
        for (int j = 0; j < OPT; j++) {
            float4 wv = *(const float4*)&Ws[(og * OPT + j) * K + k];
#pragma unroll
            for (int i = 0; i < 4; i++)
                acc[i][j] += xv[i].x * wv.x + xv[i].y * wv.y + xv[i].z * wv.z + xv[i].w * wv.w;
        }
    }
#pragma unroll
    for (int i = 0; i < 4; i++)
#pragma unroll
        for (int j = 0; j < OPT; j++)
            Y[(size_t)(base + pr + 16 * i) * N + og * OPT + j] = acc[i][j];
}

__global__ void __launch_bounds__(256) k_val(const float* __restrict__ W, const float* __restrict__ B) {
    gemm_body<128, 128>(g_h, g_v, W, B);
}
__global__ void __launch_bounds__(256) k_om(const float* __restrict__ W, const float* __restrict__ B) {
    gemm_body<128, 112>(g_dw, g_om, W, B);
}

// ------------------------- kernel 3: depthwise 3x3 SAME on g_h -> g_dw -------------------------
__global__ void __launch_bounds__(256) k_dwc(const float* __restrict__ Wd, const float* __restrict__ Bd) {
    int idx = blockIdx.x * 256 + threadIdx.x;
    int p = idx >> 7, c = idx & 127;
    int img = p / HW, p0 = p - img * HW;
    int hh = p0 / 160, ww = p0 - hh * 160;
    float acc = __ldg(&Bd[c]);
#pragma unroll
    for (int dy = 0; dy < 3; dy++) {
        int y = hh + dy - 1;
        if (y < 0 || y >= 160) continue;
#pragma unroll
        for (int dx = 0; dx < 3; dx++) {
            int x = ww + dx - 1;
            if (x < 0 || x >= 160) continue;
            acc += g_h[((size_t)img * HW + y * 160 + x) * 128 + c] * __ldg(&Wd[(dy * 3 + dx) * 128 + c]);
        }
    }
    g_dw[(size_t)idx] = acc;
}

// ------------------------- kernel 5: deformable bilinear sampling -------------------------
__global__ void __launch_bounds__(256) k_sample() {
    int tid = threadIdx.x;
    int pos = blockIdx.x * 2 + (tid >> 7);
    int g = (tid >> 5) & 3;
    int c = tid & 31;
    int img = pos / HW;
    int p0 = pos - img * HW;
    int hh = p0 / 160, ww = p0 - hh * 160;
    const float* omp = g_om + (size_t)pos * 112 + g * 27;
    const float* vg = g_v + (size_t)img * HW * 128 + g * 32 + c;
    float acc = 0.f;
#pragma unroll
    for (int k = 0; k < 9; k++) {
        float ox = __ldg(&omp[k * 3 + 0]);
        float oy = __ldg(&omp[k * 3 + 1]);
        float mk = __ldg(&omp[k * 3 + 2]);
        float fx = (float)(ww + (k % 3) - 1) + ox;    // unpadded coords
        float fy = (float)(hh + (k / 3) - 1) + oy;
        float x0f = floorf(fx), y0f = floorf(fy);
        float tx = fx - x0f, ty = fy - y0f;
        int ix = (int)x0f, iy = (int)y0f;
        float w00 = (1.f - tx) * (1.f - ty) * mk;
        float w01 = tx * (1.f - ty) * mk;
        float w10 = (1.f - tx) * ty * mk;
        float w11 = tx * ty * mk;
        if ((unsigned)iy < 160u) {
            if ((unsigned)ix < 160u)       acc += w00 * __ldg(&vg[(size_t)(iy * 160 + ix) * 128]);
            if ((unsigned)(ix + 1) < 160u) acc += w01 * __ldg(&vg[(size_t)(iy * 160 + ix + 1) * 128]);
        }
        if ((unsigned)(iy + 1) < 160u) {
            if ((unsigned)ix < 160u)       acc += w10 * __ldg(&vg[(size_t)((iy + 1) * 160 + ix) * 128]);
            if ((unsigned)(ix + 1) < 160u) acc += w11 * __ldg(&vg[(size_t)((iy + 1) * 160 + ix + 1) * 128]);
        }
    }
    g_samp[(size_t)pos * 128 + g * 32 + c] = acc;
}

// ------------------------- kernel 6: outp GEMM (128->128) + SimpleGate -> 64 -------------------------
__global__ void __launch_bounds__(256) k_outp_gate(const float* __restrict__ Wo,
                                                   const float* __restrict__ Bo) {
    extern __shared__ float sm[];
    float* Ws = sm;               // 128*128
    float* Xs = sm + 128 * 128;   // 64*132
    int tid = threadIdx.x;
    int base = blockIdx.x * 64;
    for (int i = tid; i < 128 * 128; i += 256) Ws[i] = Wo[i];
    for (int i = tid; i < 64 * 128; i += 256) {
        int p = i >> 7, k = i & 127;
        Xs[p * 132 + k] = g_samp[(size_t)(base + p) * 128 + k];
    }
    __syncthreads();
    int pr = tid & 15, og = tid >> 4;   // gate outputs j = og*4 + 0..3
    float aA[4][4], aB[4][4];
#pragma unroll
    for (int j = 0; j < 4; j++) {
        float ba = Bo[og * 4 + j], bb = Bo[og * 4 + j + 64];
#pragma unroll
        for (int i = 0; i < 4; i++) { aA[i][j] = ba; aB[i][j] = bb; }
    }
#pragma unroll 4
    for (int k = 0; k < 128; k += 4) {
        float4 xv[4];
#pragma unroll
        for (int i = 0; i < 4; i++) xv[i] = *(const float4*)&Xs[(pr + 16 * i) * 132 + k];
#pragma unroll
        for (int j = 0; j < 4; j++) {
            float4 wa = *(const float4*)&Ws[(og * 4 + j) * 128 + k];
            float4 wb = *(const float4*)&Ws[(og * 4 + j + 64) * 128 + k];
#pragma unroll
            for (int i = 0; i < 4; i++) {
                aA[i][j] += xv[i].x * wa.x + xv[i].y * wa.y + xv[i].z * wa.z + xv[i].w * wa.w;
                aB[i][j] += xv[i].x * wb.x + xv[i].y * wb.y + xv[i].z * wb.z + xv[i].w * wb.w;
            }
        }
    }
#pragma unroll
    for (int i = 0; i < 4; i++)
#pragma unroll
        for (int j = 0; j < 4; j++)
            g_f[(size_t)(base + pr + 16 * i) * 64 + og * 4 + j] = aA[i][j] * aB[i][j];
}

// ------------------------- pooling partials -------------------------
__global__ void __launch_bounds__(256) k_pool() {
    __shared__ float sh[256];
    int img = blockIdx.x >> 4, seg = blockIdx.x & 15;
    int tid = threadIdx.x;
    int c = tid & 63, q = tid >> 6;
    const float* fp = g_f + ((size_t)img * HW + seg * 1600) * 64;
    float s = 0.f;
    for (int n = 0; n < 400; n++) s += fp[(size_t)(q + 4 * n) * 64 + c];
    sh[tid] = s;
    __syncthreads();
    if (tid < 64)
        g_part[(img * 16 + seg) * 64 + tid] = sh[tid] + sh[tid + 64] + sh[tid + 128] + sh[tid + 192];
}

// ------------------------- finish pooling + SCA projection -------------------------
__global__ void __launch_bounds__(256) k_sca(const float* __restrict__ sw, const float* __restrict__ sb) {
    __shared__ float shp[256];
    int tid = threadIdx.x;
    int b = tid >> 7, c = tid & 127;
    int img = (c < 64) ? b : (2 + b);
    int cc = c & 63;
    float s = 0.f;
    for (int seg = 0; seg < 16; seg++) s += g_part[(img * 16 + seg) * 64 + cc];
    shp[tid] = s * (1.f / (float)HW);
    __syncthreads();
    float acc = __ldg(&sb[c]);
    for (int k = 0; k < 128; k++) acc += shp[b * 128 + k] * __ldg(&sw[c * 128 + k]);
    g_s[tid] = acc;
}

// ------------------------- SCA-folded conv3 + dual residual -> g_y -------------------------
__global__ void __launch_bounds__(256) k_conv3_y(const float* __restrict__ W3,
                                                 const float* __restrict__ B3,
                                                 const float* __restrict__ beta,
                                                 const float* __restrict__ x_l,
                                                 const float* __restrict__ x_r) {
    extern __shared__ float sm[];
    float* Fs = sm;              // 64*132
    float* W3s = sm + 64 * 132;  // 64*128 (scale-folded)
    int tid = threadIdx.x;
    int base = blockIdx.x * 64;
    int b = base / HW;
    int pos = base - b * HW;
    for (int i = tid; i < 64 * 128; i += 256) {
        int p = i >> 7, o = i & 127;
        float v = (o < 64) ? g_f[((size_t)b * HW + pos + p) * 64 + o]
                           : g_f[((size_t)(2 + b) * HW + pos + p) * 64 + (o - 64)];
        Fs[p * 132 + o] = v;
    }
    for (int i = tid; i < 64 * 128; i += 256) {
        int o = i & 127;
        W3s[i] = W3[i] * g_s[b * 128 + o];
    }
    __syncthreads();
    int pr = tid & 15, og = tid >> 4;   // out ch jj = og*4 + 0..3
    float acc[4][4];
#pragma unroll
    for (int j = 0; j < 4; j++) {
        float bv = B3[og * 4 + j];
#pragma unroll
        for (int i = 0; i < 4; i++) acc[i][j] = bv;
    }
#pragma unroll 4
    for (int k = 0; k < 128; k += 4) {
        float4 xv[4];
#pragma unroll
        for (int i = 0; i < 4; i++) xv[i] = *(const float4*)&Fs[(pr + 16 * i) * 132 + k];
#pragma unroll
        for (int j = 0; j < 4; j++) {
            float4 wv = *(const float4*)&W3s[(og * 4 + j) * 128 + k];
#pragma unroll
            for (int i = 0; i < 4; i++)
                acc[i][j] += xv[i].x * wv.x + xv[i].y * wv.y + xv[i].z * wv.z + xv[i].w * wv.w;
        }
    }
#pragma unroll
    for (int i = 0; i < 4; i++) {
        int p = pr + 16 * i;
#pragma unroll
        for (int j = 0; j < 4; j++) {
            int jj = og * 4 + j;
            float bt = __ldg(&beta[jj]);
            float x3 = acc[i][j] * bt;
            float xl = x_l[((size_t)b * 64 + jj) * HW + pos + p];
            float xr = x_r[((size_t)b * 64 + jj) * HW + pos + p];
            g_y[(size_t)(base + p) * 128 + jj] = xl + x3;
            g_y[(size_t)(base + p) * 128 + 64 + jj] = xr + x3;
        }
    }
}

// ------------------------- LN2(128ch) + conv4 + gate -> g_zg -------------------------
__global__ void __launch_bounds__(256) k_ln2c4(const float* __restrict__ g2,
                                               const float* __restrict__ W4,
                                               const float* __restrict__ B4) {
    extern __shared__ float sm[];
    float* Ys = sm;               // 64*132
    float* Ws = sm + 64 * 132;    // 128*128
    float* mr = Ws + 128 * 128;   // 128
    int tid = threadIdx.x;
    int base = blockIdx.x * 64;
    for (int i = tid; i < 64 * 128; i += 256) {
        int p = i >> 7, c = i & 127;
        Ys[p * 132 + c] = g_y[(size_t)(base + p) * 128 + c];
    }
    for (int i = tid; i < 128 * 128; i += 256) Ws[i] = W4[i];
    __syncthreads();
    if (tid < 64) {
        float s = 0.f, sq = 0.f;
        for (int c = 0; c < 128; c++) { float v = Ys[tid * 132 + c]; s += v; sq += v * v; }
        float m = s * (1.f / 128.f);
        float var = sq * (1.f / 128.f) - m * m;
        mr[tid] = m; mr[64 + tid] = rsqrtf(var + 1e-5f);
    }
    __syncthreads();
    for (int i = tid; i < 64 * 128; i += 256) {
        int p = i >> 7, c = i & 127;
        Ys[p * 132 + c] = (Ys[p * 132 + c] - mr[p]) * mr[64 + p] * __ldg(&g2[c]);
    }
    __syncthreads();
    int pr = tid & 15, og = tid >> 4;   // gate outputs j = og*4 + 0..3
    float aA[4][4], aB[4][4];
#pragma unroll
    for (int j = 0; j < 4; j++) {
        float ba = B4[og * 4 + j], bb = B4[og * 4 + j + 64];
#pragma unroll
        for (int i = 0; i < 4; i++) { aA[i][j] = ba; aB[i][j] = bb; }
    }
#pragma unroll 4
    for (int k = 0; k < 128; k += 4) {
        float4 xv[4];
#pragma unroll
        for (int i = 0; i < 4; i++) xv[i] = *(const float4*)&Ys[(pr + 16 * i) * 132 + k];
#pragma unroll
        for (int j = 0; j < 4; j++) {
            float4 wa = *(const float4*)&Ws[(og * 4 + j) * 128 + k];
            float4 wb = *(const float4*)&Ws[(og * 4 + j + 64) * 128 + k];
#pragma unroll
            for (int i = 0; i < 4; i++) {
                aA[i][j] += xv[i].x * wa.x + xv[i].y * wa.y + xv[i].z * wa.z + xv[i].w * wa.w;
                aB[i][j] += xv[i].x * wb.x + xv[i].y * wb.y + xv[i].z * wb.z + xv[i].w * wb.w;
            }
        }
    }
#pragma unroll
    for (int i = 0; i < 4; i++)
#pragma unroll
        for (int j = 0; j < 4; j++)
            g_zg[(size_t)(base + pr + 16 * i) * 64 + og * 4 + j] = aA[i][j] * aB[i][j];
}

// ------------------------- conv5 + final residuals, NCHW outputs -------------------------
__global__ void __launch_bounds__(256) k_c5out(const float* __restrict__ W5,
                                               const float* __restrict__ B5,
                                               const float* __restrict__ gamma,
                                               float* __restrict__ out) {
    extern __shared__ float sm[];
    float* Zs = sm;                    // 64*68
    float* W5s = sm + 64 * 68;         // 64*64
    float* Ys = W5s + 64 * 64;         // 64*132
    int tid = threadIdx.x;
    int base = blockIdx.x * 64;
    int b = base / HW;
    int pos = base - b * HW;
    for (int i = tid; i < 64 * 64; i += 256) {
        int p = i >> 6, k = i & 63;
        Zs[p * 68 + k] = g_zg[(size_t)(base + p) * 64 + k];
    }
    for (int i = tid; i < 64 * 64; i += 256) W5s[i] = W5[i];
    for (int i = tid; i < 64 * 128; i += 256) {
        int p = i >> 7, c = i & 127;
        Ys[p * 132 + c] = g_y[(size_t)(base + p) * 128 + c];
    }
    __syncthreads();
    int pr = tid & 15, og = tid >> 4;   // out ch cc = og*4 + 0..3
    float acc[4][4];
#pragma unroll
    for (int j = 0; j < 4; j++) {
        float bv = B5[og * 4 + j];
#pragma unroll
        for (int i = 0; i < 4; i++) acc[i][j] = bv;
    }
#pragma unroll 4
    for (int k = 0; k < 64; k += 4) {
        float4 xv[4];
#pragma unroll
        for (int i = 0; i < 4; i++) xv[i] = *(const float4*)&Zs[(pr + 16 * i) * 68 + k];
#pragma unroll
        for (int j = 0; j < 4; j++) {
            float4 wv = *(const float4*)&W5s[(og * 4 + j) * 64 + k];
#pragma unroll
            for (int i = 0; i < 4; i++)
                acc[i][j] += xv[i].x * wv.x + xv[i].y * wv.y + xv[i].z * wv.z + xv[i].w * wv.w;
        }
    }
    const size_t HALF = (size_t)2 * 64 * HW;   // elements in out_l
#pragma unroll
    for (int i = 0; i < 4; i++) {
        int p = pr + 16 * i;
#pragma unroll
        for (int j = 0; j < 4; j++) {
            int cc = og * 4 + j;
            float z = acc[i][j] * __ldg(&gamma[cc]);
            size_t o = ((size_t)b * 64 + cc) * HW + pos + p;
            out[o] = Ys[p * 132 + cc] + z;
            out[HALF + o] = Ys[p * 132 + 64 + cc] + z;
        }
    }
}

// ------------------------- host -------------------------
extern "C" void kernel_launch(void* const* d_in, const int* in_sizes, int n_in,
                              void* d_out, int out_size) {
    const float* x_l     = (const float*)d_in[0];
    const float* x_r     = (const float*)d_in[1];
    const float* ln1_g   = (const float*)d_in[2];
    const float* pw1_w   = (const float*)d_in[3];
    const float* pw1_b   = (const float*)d_in[4];
    const float* val_w   = (const float*)d_in[5];
    const float* val_b   = (const float*)d_in[6];
    const float* dwc_w   = (const float*)d_in[7];
    const float* dwc_b   = (const float*)d_in[8];
    const float* om_w    = (const float*)d_in[9];
    const float* om_b    = (const float*)d_in[10];
    const float* outp_w  = (const float*)d_in[11];
    const float* outp_b  = (const float*)d_in[12];
    const float* sca_w   = (const float*)d_in[13];
    const float* sca_b   = (const float*)d_in[14];
    const float* conv3_w = (const float*)d_in[15];
    const float* conv3_b = (const float*)d_in[16];
    const float* norm2_g = (const float*)d_in[17];
    const float* conv4_w = (const float*)d_in[18];
    const float* conv4_b = (const float*)d_in[19];
    const float* conv5_w = (const float*)d_in[20];
    const float* conv5_b = (const float*)d_in[21];
    const float* beta    = (const float*)d_in[22];
    const float* gamma   = (const float*)d_in[23];
    float* out = (float*)d_out;

    const int SM_LNPW1 = (64 * 68 + 128 * 64 + 128) * 4;            // 50688
    const int SM_VAL   = (128 * 128 + 64 * 132) * 4;                // 99328
    const int SM_OM    = (112 * 128 + 64 * 132) * 4;                // 91136
    const int SM_OUTP  = (128 * 128 + 64 * 132) * 4;                // 99328
    const int SM_C3    = (64 * 132 + 64 * 128) * 4;                 // 66560
    const int SM_LN2   = (64 * 132 + 128 * 128 + 128) * 4;          // 99840
    const int SM_C5    = (64 * 68 + 64 * 64 + 64 * 132) * 4;        // 67584

    cudaFuncSetAttribute(k_ln_pw1,    cudaFuncAttributeMaxDynamicSharedMemorySize, SM_LNPW1);
    cudaFuncSetAttribute(k_val,       cudaFuncAttributeMaxDynamicSharedMemorySize, SM_VAL);
    cudaFuncSetAttribute(k_om,        cudaFuncAttributeMaxDynamicSharedMemorySize, SM_OM);
    cudaFuncSetAttribute(k_outp_gate, cudaFuncAttributeMaxDynamicSharedMemorySize, SM_OUTP);
    cudaFuncSetAttribute(k_conv3_y,   cudaFuncAttributeMaxDynamicSharedMemorySize, SM_C3);
    cudaFuncSetAttribute(k_ln2c4,     cudaFuncAttributeMaxDynamicSharedMemorySize, SM_LN2);
    cudaFuncSetAttribute(k_c5out,     cudaFuncAttributeMaxDynamicSharedMemorySize, SM_C5);

    k_ln_pw1   <<<P4 / 64, 256, SM_LNPW1>>>(x_l, x_r, ln1_g, pw1_w, pw1_b);
    k_val      <<<P4 / 64, 256, SM_VAL>>>(val_w, val_b);
    k_dwc      <<<P4 * 128 / 256, 256>>>(dwc_w, dwc_b);
    k_om       <<<P4 / 64, 256, SM_OM>>>(om_w, om_b);
    k_sample   <<<P4 / 2, 256>>>();
    k_outp_gate<<<P4 / 64, 256, SM_OUTP>>>(outp_w, outp_b);
    k_pool     <<<64, 256>>>();
    k_sca      <<<1, 256>>>(sca_w, sca_b);
    k_conv3_y  <<<P2 / 64, 256, SM_C3>>>(conv3_w, conv3_b, beta, x_l, x_r);
    k_ln2c4    <<<P2 / 64, 256, SM_LN2>>>(norm2_g, conv4_w, conv4_b);
    k_c5out    <<<P2 / 64, 256, SM_C5>>>(conv5_w, conv5_b, gamma, out);
}

// round 3
// speedup vs baseline: 1.0387x; 1.0387x over previous
#include <cuda_runtime.h>
#include <cstdint>

#define HW 25600
#define P4 102400   // 4 images * HW  (img 0,1 = x_l b0,b1 ; img 2,3 = x_r b0,b1)
#define P2 51200    // 2 batches * HW

// ------------------------- scratch (__device__ globals) -------------------------
__device__ float g_h[(size_t)P4 * 128];     // LN1+pw1 out, NHWC
__device__ float g_v[(size_t)P4 * 128];     // value proj
__device__ float g_dw[(size_t)P4 * 128];    // depthwise conv out
__device__ float g_om[(size_t)P4 * 112];    // offset/mask proj (first 108 used)
__device__ float g_f[(size_t)P4 * 64];      // gated branch features
__device__ float g_y[(size_t)P2 * 128];     // [y_l(64) ; y_r(64)] NHWC per batch
__device__ float g_zg[(size_t)P2 * 64];     // gated conv4 output
__device__ float g_part[64 * 64];           // pooling partials [img*16+seg][64]
__device__ float g_s[256];                  // SCA scale s[b][128]

// ------------------------- cp.async helpers -------------------------
__device__ __forceinline__ void cp16(void* dst, const void* src) {
    uint32_t d = (uint32_t)__cvta_generic_to_shared(dst);
    asm volatile("cp.async.cg.shared.global [%0], [%1], 16;\n" :: "r"(d), "l"(src));
}
#define CP_COMMIT asm volatile("cp.async.commit_group;\n")
#define CP_WAIT0  asm volatile("cp.async.wait_group 0;\n")

// ------------------------- kernel 1: LN(64ch) + pw1 (64 -> 128) -------------------------
__global__ void __launch_bounds__(256) k_ln_pw1(const float* __restrict__ x_l,
                                                const float* __restrict__ x_r,
                                                const float* __restrict__ g1,
                                                const float* __restrict__ W,
                                                const float* __restrict__ Bb) {
    extern __shared__ float sm[];
    float* Xs = sm;                  // 64 px * 68
    float* Ws = sm + 64 * 68;        // 128*64
    float* mr = Ws + 128 * 64;       // 128
    int tid = threadIdx.x;
    int base = blockIdx.x * 64;
    int img = base / HW;
    int pos = base - img * HW;
    const float* xp = (img < 2) ? (x_l + (size_t)img * HW * 64)
                                : (x_r + (size_t)(img - 2) * HW * 64);
    for (int i = tid; i < 64 * 64; i += 256) {
        int c = i >> 6, p = i & 63;
        Xs[p * 68 + c] = xp[(size_t)c * HW + pos + p];
    }
    for (int i = tid; i < 128 * 64; i += 256) Ws[i] = W[i];
    __syncthreads();
    if (tid < 64) {
        float s = 0.f, sq = 0.f;
        for (int c = 0; c < 64; c++) { float v = Xs[tid * 68 + c]; s += v; sq += v * v; }
        float m = s * (1.f / 64.f);
        float var = sq * (1.f / 64.f) - m * m;
        mr[tid] = m; mr[64 + tid] = rsqrtf(var + 1e-5f);
    }
    __syncthreads();
    for (int i = tid; i < 64 * 64; i += 256) {
        int p = i >> 6, c = i & 63;
        Xs[p * 68 + c] = (Xs[p * 68 + c] - mr[p]) * mr[64 + p] * __ldg(&g1[c]);
    }
    __syncthreads();
    int pr = tid & 15, og = tid >> 4;
    float acc[4][8];
#pragma unroll
    for (int j = 0; j < 8; j++) {
        float b = Bb[og * 8 + j];
#pragma unroll
        for (int i = 0; i < 4; i++) acc[i][j] = b;
    }
#pragma unroll 4
    for (int k = 0; k < 64; k += 4) {
        float4 xv[4];
#pragma unroll
        for (int i = 0; i < 4; i++) xv[i] = *(const float4*)&Xs[(pr + 16 * i) * 68 + k];
#pragma unroll
        for (int j = 0; j < 8; j++) {
            float4 wv = *(const float4*)&Ws[(og * 8 + j) * 64 + k];
#pragma unroll
            for (int i = 0; i < 4; i++)
                acc[i][j] += xv[i].x * wv.x + xv[i].y * wv.y + xv[i].z * wv.z + xv[i].w * wv.w;
        }
    }
#pragma unroll
    for (int i = 0; i < 4; i++)
#pragma unroll
        for (int j = 0; j < 8; j++)
            g_h[(size_t)(base + pr + 16 * i) * 128 + og * 8 + j] = acc[i][j];
}

// ------------------------- big GEMM: 128 px/block, 8px x 8out per thread, K=128 -------------------------
template <int N>
__global__ void __launch_bounds__(256) k_gemm128(const float* __restrict__ X,
                                                 float* __restrict__ Y,
                                                 const float* __restrict__ W,
                                                 const float* __restrict__ Bb) {
    extern __shared__ float sm[];
    float* Ws = sm;                  // 128*128 (rows >= N zero-filled)
    float* Xs = sm + 128 * 128;      // 128*(128+4)
    int tid = threadIdx.x;
    size_t base = (size_t)blockIdx.x * 128;
    // async-load X tile (128 rows x 128 k)
    for (int i = tid; i < 4096; i += 256) {
        int row = i >> 5, c4 = i & 31;
        cp16(&Xs[row * 132 + c4 * 4], &X[(base + row) * 128 + c4 * 4]);
    }
    CP_COMMIT;
    // load weights (overlaps with async copy)
    for (int i = tid; i < N * 128; i += 256) Ws[i] = W[i];
    if (N < 128)
        for (int i = N * 128 + tid; i < 128 * 128; i += 256) Ws[i] = 0.f;
    CP_WAIT0;
    __syncthreads();
    int pr = tid & 15, og = tid >> 4;
    float acc[8][8];
#pragma unroll
    for (int j = 0; j < 8; j++) {
        int o = og * 8 + j;
        float b = (o < N) ? Bb[o] : 0.f;
#pragma unroll
        for (int i = 0; i < 8; i++) acc[i][j] = b;
    }
    for (int k = 0; k < 128; k += 4) {
        float4 xv[8];
#pragma unroll
        for (int i = 0; i < 8; i++) xv[i] = *(const float4*)&Xs[(pr + 16 * i) * 132 + k];
#pragma unroll
        for (int j = 0; j < 8; j++) {
            float4 wv = *(const float4*)&Ws[(og * 8 + j) * 128 + k];
#pragma unroll
            for (int i = 0; i < 8; i++)
                acc[i][j] += xv[i].x * wv.x + xv[i].y * wv.y + xv[i].z * wv.z + xv[i].w * wv.w;
        }
    }
#pragma unroll
    for (int i = 0; i < 8; i++) {
        size_t p = base + pr + 16 * i;
#pragma unroll
        for (int j = 0; j < 8; j++) {
            int o = og * 8 + j;
            if (o < N) Y[p * N + o] = acc[i][j];
        }
    }
}

// ------------------------- depthwise 3x3, 4 px per thread -------------------------
__global__ void __launch_bounds__(256) k_dwc4(const float* __restrict__ Wd,
                                              const float* __restrict__ Bd) {
    int linear = blockIdx.x * 256 + threadIdx.x;
    int c = linear & 127;
    int pq = linear >> 7;            // quad index
    int img = pq / 6400;
    int q = pq - img * 6400;
    int h = q / 40;
    int w4 = (q - h * 40) * 4;
    float wt[9];
#pragma unroll
    for (int t = 0; t < 9; t++) wt[t] = __ldg(&Wd[t * 128 + c]);
    float a[4];
    float bv = __ldg(&Bd[c]);
#pragma unroll
    for (int j = 0; j < 4; j++) a[j] = bv;
    const float* basep = g_h + (size_t)img * HW * 128 + c;
#pragma unroll
    for (int dy = 0; dy < 3; dy++) {
        int y = h + dy - 1;
        if ((unsigned)y >= 160u) continue;
        const float* row = basep + (size_t)y * 160 * 128;
#pragma unroll
        for (int t = 0; t < 6; t++) {
            int x = w4 + t - 1;
            if ((unsigned)x >= 160u) continue;
            float v = __ldg(&row[(size_t)x * 128]);
#pragma unroll
            for (int j = 0; j < 4; j++) {
                int dx = t - j;                 // tap column for pixel j
                if (dx >= 0 && dx <= 2) a[j] += v * wt[dy * 3 + dx];
            }
        }
    }
    size_t o = ((size_t)pq * 4) * 128 + c;
#pragma unroll
    for (int j = 0; j < 4; j++) g_dw[o + (size_t)j * 128] = a[j];
}

// ------------------------- fused: deformable sample + outp GEMM + SimpleGate -------------------------
__device__ __forceinline__ void fma4(float4& a, float w, const float4 v) {
    a.x += w * v.x; a.y += w * v.y; a.z += w * v.z; a.w += w * v.w;
}

__global__ void __launch_bounds__(256) k_souter(const float* __restrict__ Wo,
                                                const float* __restrict__ Bo) {
    extern __shared__ float sm[];
    float* Ws = sm;                   // 128*128
    float* Xs = sm + 16384;           // 64*132 sampled features
    float* OMs = Xs + 64 * 132;       // 8 warps * 112
    int tid = threadIdx.x;
    int base = blockIdx.x * 64;
    int img = base / HW;
    int pbase = base - img * HW;
    // kick off weight load (no sync needed until GEMM phase)
    for (int i = tid; i < 16384; i += 256) Ws[i] = Wo[i];
    // --- sampling phase: warp w handles px w*8 .. w*8+7; lane -> (g, c4) ---
    int wrp = tid >> 5, lane = tid & 31;
    int g = lane >> 3, c4 = lane & 7;
    const float* vg = g_v + (size_t)img * HW * 128 + g * 32 + c4 * 4;
    float* oms = OMs + wrp * 112;
    for (int p8 = 0; p8 < 8; p8++) {
        int px = wrp * 8 + p8;
        int pos = pbase + px;
        int hh = pos / 160, ww = pos - hh * 160;
        const float* omp = g_om + ((size_t)img * HW + pos) * 112;
        __syncwarp();
        oms[lane] = omp[lane];
        oms[32 + lane] = omp[32 + lane];
        oms[64 + lane] = omp[64 + lane];
        if (lane < 12) oms[96 + lane] = omp[96 + lane];
        __syncwarp();
        float4 acc = make_float4(0.f, 0.f, 0.f, 0.f);
#pragma unroll
        for (int k = 0; k < 9; k++) {
            float ox = oms[g * 27 + k * 3 + 0];
            float oy = oms[g * 27 + k * 3 + 1];
            float mk = oms[g * 27 + k * 3 + 2];
            float fx = (float)(ww + (k % 3) - 1) + ox;
            float fy = (float)(hh + (k / 3) - 1) + oy;
            float x0f = floorf(fx), y0f = floorf(fy);
            float tx = fx - x0f, ty = fy - y0f;
            int ix = (int)x0f, iy = (int)y0f;
            float w00 = (1.f - tx) * (1.f - ty) * mk;
            float w01 = tx * (1.f - ty) * mk;
            float w10 = (1.f - tx) * ty * mk;
            float w11 = tx * ty * mk;
            if ((unsigned)iy < 160u) {
                if ((unsigned)ix < 160u)
                    fma4(acc, w00, *(const float4*)&vg[(size_t)(iy * 160 + ix) * 128]);
                if ((unsigned)(ix + 1) < 160u)
                    fma4(acc, w01, *(const float4*)&vg[(size_t)(iy * 160 + ix + 1) * 128]);
            }
            if ((unsigned)(iy + 1) < 160u) {
                if ((unsigned)ix < 160u)
                    fma4(acc, w10, *(const float4*)&vg[(size_t)((iy + 1) * 160 + ix) * 128]);
                if ((unsigned)(ix + 1) < 160u)
                    fma4(acc, w11, *(const float4*)&vg[(size_t)((iy + 1) * 160 + ix + 1) * 128]);
            }
        }
        *(float4*)&Xs[px * 132 + lane * 4] = acc;
    }
    __syncthreads();
    // --- GEMM + gate phase ---
    int pr = tid & 15, og = tid >> 4;
    float aA[4][4], aB[4][4];
#pragma unroll
    for (int j = 0; j < 4; j++) {
        float ba = Bo[og * 4 + j], bb = Bo[og * 4 + j + 64];
#pragma unroll
        for (int i = 0; i < 4; i++) { aA[i][j] = ba; aB[i][j] = bb; }
    }
#pragma unroll 4
    for (int k = 0; k < 128; k += 4) {
        float4 xv[4];
#pragma unroll
        for (int i = 0; i < 4; i++) xv[i] = *(const float4*)&Xs[(pr + 16 * i) * 132 + k];
#pragma unroll
        for (int j = 0; j < 4; j++) {
            float4 wa = *(const float4*)&Ws[(og * 4 + j) * 128 + k];
            float4 wb = *(const float4*)&Ws[(og * 4 + j + 64) * 128 + k];
#pragma unroll
            for (int i = 0; i < 4; i++) {
                aA[i][j] += xv[i].x * wa.x + xv[i].y * wa.y + xv[i].z * wa.z + xv[i].w * wa.w;
                aB[i][j] += xv[i].x * wb.x + xv[i].y * wb.y + xv[i].z * wb.z + xv[i].w * wb.w;
            }
        }
    }
#pragma unroll
    for (int i = 0; i < 4; i++)
#pragma unroll
        for (int j = 0; j < 4; j++)
            g_f[(size_t)(base + pr + 16 * i) * 64 + og * 4 + j] = aA[i][j] * aB[i][j];
}

// ------------------------- pooling partials -------------------------
__global__ void __launch_bounds__(256) k_pool() {
    __shared__ float sh[256];
    int img = blockIdx.x >> 4, seg = blockIdx.x & 15;
    int tid = threadIdx.x;
    int c = tid & 63, q = tid >> 6;
    const float* fp = g_f + ((size_t)img * HW + seg * 1600) * 64;
    float s = 0.f;
    for (int n = 0; n < 400; n++) s += fp[(size_t)(q + 4 * n) * 64 + c];
    sh[tid] = s;
    __syncthreads();
    if (tid < 64)
        g_part[(img * 16 + seg) * 64 + tid] = sh[tid] + sh[tid + 64] + sh[tid + 128] + sh[tid + 192];
}

// ------------------------- finish pooling + SCA projection -------------------------
__global__ void __launch_bounds__(256) k_sca(const float* __restrict__ sw, const float* __restrict__ sb) {
    __shared__ float shp[256];
    int tid = threadIdx.x;
    int b = tid >> 7, c = tid & 127;
    int img = (c < 64) ? b : (2 + b);
    int cc = c & 63;
    float s = 0.f;
    for (int seg = 0; seg < 16; seg++) s += g_part[(img * 16 + seg) * 64 + cc];
    shp[tid] = s * (1.f / (float)HW);
    __syncthreads();
    float acc = __ldg(&sb[c]);
    for (int k = 0; k < 128; k++) acc += shp[b * 128 + k] * __ldg(&sw[c * 128 + k]);
    g_s[tid] = acc;
}

// ------------------------- SCA-folded conv3 + dual residual -> g_y -------------------------
__global__ void __launch_bounds__(256) k_conv3_y(const float* __restrict__ W3,
                                                 const float* __restrict__ B3,
                                                 const float* __restrict__ beta,
                                                 const float* __restrict__ x_l,
                                                 const float* __restrict__ x_r) {
    extern __shared__ float sm[];
    float* Fs = sm;              // 64*132
    float* W3s = sm + 64 * 132;  // 64*128 (scale-folded)
    int tid = threadIdx.x;
    int base = blockIdx.x * 64;
    int b = base / HW;
    int pos = base - b * HW;
    for (int i = tid; i < 64 * 128; i += 256) {
        int p = i >> 7, o = i & 127;
        float v = (o < 64) ? g_f[((size_t)b * HW + pos + p) * 64 + o]
                           : g_f[((size_t)(2 + b) * HW + pos + p) * 64 + (o - 64)];
        Fs[p * 132 + o] = v;
    }
    for (int i = tid; i < 64 * 128; i += 256) {
        int o = i & 127;
        W3s[i] = W3[i] * g_s[b * 128 + o];
    }
    __syncthreads();
    int pr = tid & 15, og = tid >> 4;
    float acc[4][4];
#pragma unroll
    for (int j = 0; j < 4; j++) {
        float bv = B3[og * 4 + j];
#pragma unroll
        for (int i = 0; i < 4; i++) acc[i][j] = bv;
    }
#pragma unroll 4
    for (int k = 0; k < 128; k += 4) {
        float4 xv[4];
#pragma unroll
        for (int i = 0; i < 4; i++) xv[i] = *(const float4*)&Fs[(pr + 16 * i) * 132 + k];
#pragma unroll
        for (int j = 0; j < 4; j++) {
            float4 wv = *(const float4*)&W3s[(og * 4 + j) * 128 + k];
#pragma unroll
            for (int i = 0; i < 4; i++)
                acc[i][j] += xv[i].x * wv.x + xv[i].y * wv.y + xv[i].z * wv.z + xv[i].w * wv.w;
        }
    }
#pragma unroll
    for (int i = 0; i < 4; i++) {
        int p = pr + 16 * i;
#pragma unroll
        for (int j = 0; j < 4; j++) {
            int jj = og * 4 + j;
            float bt = __ldg(&beta[jj]);
            float x3 = acc[i][j] * bt;
            float xl = x_l[((size_t)b * 64 + jj) * HW + pos + p];
            float xr = x_r[((size_t)b * 64 + jj) * HW + pos + p];
            g_y[(size_t)(base + p) * 128 + jj] = xl + x3;
            g_y[(size_t)(base + p) * 128 + 64 + jj] = xr + x3;
        }
    }
}

// ------------------------- LN2(128ch) + conv4 + gate -> g_zg -------------------------
__global__ void __launch_bounds__(256) k_ln2c4(const float* __restrict__ g2,
                                               const float* __restrict__ W4,
                                               const float* __restrict__ B4) {
    extern __shared__ float sm[];
    float* Ys = sm;               // 64*132
    float* Ws = sm + 64 * 132;    // 128*128
    float* mr = Ws + 128 * 128;   // 128
    int tid = threadIdx.x;
    int base = blockIdx.x * 64;
    for (int i = tid; i < 64 * 128; i += 256) {
        int p = i >> 7, c = i & 127;
        Ys[p * 132 + c] = g_y[(size_t)(base + p) * 128 + c];
    }
    for (int i = tid; i < 128 * 128; i += 256) Ws[i] = W4[i];
    __syncthreads();
    if (tid < 64) {
        float s = 0.f, sq = 0.f;
        for (int c = 0; c < 128; c++) { float v = Ys[tid * 132 + c]; s += v; sq += v * v; }
        float m = s * (1.f / 128.f);
        float var = sq * (1.f / 128.f) - m * m;
        mr[tid] = m; mr[64 + tid] = rsqrtf(var + 1e-5f);
    }
    __syncthreads();
    for (int i = tid; i < 64 * 128; i += 256) {
        int p = i >> 7, c = i & 127;
        Ys[p * 132 + c] = (Ys[p * 132 + c] - mr[p]) * mr[64 + p] * __ldg(&g2[c]);
    }
    __syncthreads();
    int pr = tid & 15, og = tid >> 4;
    float aA[4][4], aB[4][4];
#pragma unroll
    for (int j = 0; j < 4; j++) {
        float ba = B4[og * 4 + j], bb = B4[og * 4 + j + 64];
#pragma unroll
        for (int i = 0; i < 4; i++) { aA[i][j] = ba; aB[i][j] = bb; }
    }
#pragma unroll 4
    for (int k = 0; k < 128; k += 4) {
        float4 xv[4];
#pragma unroll
        for (int i = 0; i < 4; i++) xv[i] = *(const float4*)&Ys[(pr + 16 * i) * 132 + k];
#pragma unroll
        for (int j = 0; j < 4; j++) {
            float4 wa = *(const float4*)&Ws[(og * 4 + j) * 128 + k];
            float4 wb = *(const float4*)&Ws[(og * 4 + j + 64) * 128 + k];
#pragma unroll
            for (int i = 0; i < 4; i++) {
                aA[i][j] += xv[i].x * wa.x + xv[i].y * wa.y + xv[i].z * wa.z + xv[i].w * wa.w;
                aB[i][j] += xv[i].x * wb.x + xv[i].y * wb.y + xv[i].z * wb.z + xv[i].w * wb.w;
            }
        }
    }
#pragma unroll
    for (int i = 0; i < 4; i++)
#pragma unroll
        for (int j = 0; j < 4; j++)
            g_zg[(size_t)(base + pr + 16 * i) * 64 + og * 4 + j] = aA[i][j] * aB[i][j];
}

// ------------------------- conv5 + final residuals, NCHW outputs -------------------------
__global__ void __launch_bounds__(256) k_c5out(const float* __restrict__ W5,
                                               const float* __restrict__ B5,
                                               const float* __restrict__ gamma,
                                               float* __restrict__ out) {
    extern __shared__ float sm[];
    float* Zs = sm;                    // 64*68
    float* W5s = sm + 64 * 68;         // 64*64
    float* Ys = W5s + 64 * 64;         // 64*132
    int tid = threadIdx.x;
    int base = blockIdx.x * 64;
    int b = base / HW;
    int pos = base - b * HW;
    for (int i = tid; i < 64 * 64; i += 256) {
        int p = i >> 6, k = i & 63;
        Zs[p * 68 + k] = g_zg[(size_t)(base + p) * 64 + k];
    }
    for (int i = tid; i < 64 * 64; i += 256) W5s[i] = W5[i];
    for (int i = tid; i < 64 * 128; i += 256) {
        int p = i >> 7, c = i & 127;
        Ys[p * 132 + c] = g_y[(size_t)(base + p) * 128 + c];
    }
    __syncthreads();
    int pr = tid & 15, og = tid >> 4;
    float acc[4][4];
#pragma unroll
    for (int j = 0; j < 4; j++) {
        float bv = B5[og * 4 + j];
#pragma unroll
        for (int i = 0; i < 4; i++) acc[i][j] = bv;
    }
#pragma unroll 4
    for (int k = 0; k < 64; k += 4) {
        float4 xv[4];
#pragma unroll
        for (int i = 0; i < 4; i++) xv[i] = *(const float4*)&Zs[(pr + 16 * i) * 68 + k];
#pragma unroll
        for (int j = 0; j < 4; j++) {
            float4 wv = *(const float4*)&W5s[(og * 4 + j) * 64 + k];
#pragma unroll
            for (int i = 0; i < 4; i++)
                acc[i][j] += xv[i].x * wv.x + xv[i].y * wv.y + xv[i].z * wv.z + xv[i].w * wv.w;
        }
    }
    const size_t HALF = (size_t)2 * 64 * HW;
#pragma unroll
    for (int i = 0; i < 4; i++) {
        int p = pr + 16 * i;
#pragma unroll
        for (int j = 0; j < 4; j++) {
            int cc = og * 4 + j;
            float z = acc[i][j] * __ldg(&gamma[cc]);
            size_t o = ((size_t)b * 64 + cc) * HW + pos + p;
            out[o] = Ys[p * 132 + cc] + z;
            out[HALF + o] = Ys[p * 132 + 64 + cc] + z;
        }
    }
}

// ------------------------- host -------------------------
extern "C" void kernel_launch(void* const* d_in, const int* in_sizes, int n_in,
                              void* d_out, int out_size) {
    const float* x_l     = (const float*)d_in[0];
    const float* x_r     = (const float*)d_in[1];
    const float* ln1_g   = (const float*)d_in[2];
    const float* pw1_w   = (const float*)d_in[3];
    const float* pw1_b   = (const float*)d_in[4];
    const float* val_w   = (const float*)d_in[5];
    const float* val_b   = (const float*)d_in[6];
    const float* dwc_w   = (const float*)d_in[7];
    const float* dwc_b   = (const float*)d_in[8];
    const float* om_w    = (const float*)d_in[9];
    const float* om_b    = (const float*)d_in[10];
    const float* outp_w  = (const float*)d_in[11];
    const float* outp_b  = (const float*)d_in[12];
    const float* sca_w   = (const float*)d_in[13];
    const float* sca_b   = (const float*)d_in[14];
    const float* conv3_w = (const float*)d_in[15];
    const float* conv3_b = (const float*)d_in[16];
    const float* norm2_g = (const float*)d_in[17];
    const float* conv4_w = (const float*)d_in[18];
    const float* conv4_b = (const float*)d_in[19];
    const float* conv5_w = (const float*)d_in[20];
    const float* conv5_b = (const float*)d_in[21];
    const float* beta    = (const float*)d_in[22];
    const float* gamma   = (const float*)d_in[23];
    float* out = (float*)d_out;

    // resolve scratch pointers for gemm args
    float *ph, *pv, *pdw, *pom;
    cudaGetSymbolAddress((void**)&ph, g_h);
    cudaGetSymbolAddress((void**)&pv, g_v);
    cudaGetSymbolAddress((void**)&pdw, g_dw);
    cudaGetSymbolAddress((void**)&pom, g_om);

    const int SM_LNPW1 = (64 * 68 + 128 * 64 + 128) * 4;
    const int SM_G128  = (128 * 128 + 128 * 132) * 4;               // 133120
    const int SM_SOUT  = (128 * 128 + 64 * 132 + 8 * 112) * 4;      // 102912
    const int SM_C3    = (64 * 132 + 64 * 128) * 4;
    const int SM_LN2   = (64 * 132 + 128 * 128 + 128) * 4;
    const int SM_C5    = (64 * 68 + 64 * 64 + 64 * 132) * 4;

    cudaFuncSetAttribute(k_ln_pw1,      cudaFuncAttributeMaxDynamicSharedMemorySize, SM_LNPW1);
    cudaFuncSetAttribute(k_gemm128<128>, cudaFuncAttributeMaxDynamicSharedMemorySize, SM_G128);
    cudaFuncSetAttribute(k_gemm128<112>, cudaFuncAttributeMaxDynamicSharedMemorySize, SM_G128);
    cudaFuncSetAttribute(k_souter,      cudaFuncAttributeMaxDynamicSharedMemorySize, SM_SOUT);
    cudaFuncSetAttribute(k_conv3_y,     cudaFuncAttributeMaxDynamicSharedMemorySize, SM_C3);
    cudaFuncSetAttribute(k_ln2c4,       cudaFuncAttributeMaxDynamicSharedMemorySize, SM_LN2);
    cudaFuncSetAttribute(k_c5out,       cudaFuncAttributeMaxDynamicSharedMemorySize, SM_C5);

    k_ln_pw1      <<<P4 / 64, 256, SM_LNPW1>>>(x_l, x_r, ln1_g, pw1_w, pw1_b);
    k_gemm128<128><<<P4 / 128, 256, SM_G128>>>(ph, pv, val_w, val_b);      // value proj
    k_dwc4        <<<P4 * 128 / (256 * 4), 256>>>(dwc_w, dwc_b);
    k_gemm128<112><<<P4 / 128, 256, SM_G128>>>(pdw, pom, om_w, om_b);      // offset/mask proj
    k_souter      <<<P4 / 64, 256, SM_SOUT>>>(outp_w, outp_b);
    k_pool        <<<64, 256>>>();
    k_sca         <<<1, 256>>>(sca_w, sca_b);
    k_conv3_y     <<<P2 / 64, 256, SM_C3>>>(conv3_w, conv3_b, beta, x_l, x_r);
    k_ln2c4       <<<P2 / 64, 256, SM_LN2>>>(norm2_g, conv4_w, conv4_b);
    k_c5out       <<<P2 / 64, 256, SM_C5>>>(conv5_w, conv5_b, gamma, out);
}

// round 4
// speedup vs baseline: 1.1911x; 1.1467x over previous
#include <cuda_runtime.h>
#include <cstdint>

#define HW 25600
#define P4 102400   // 4 images * HW  (img 0,1 = x_l b0,b1 ; img 2,3 = x_r b0,b1)
#define P2 51200    // 2 batches * HW

// ------------------------- scratch (__device__ globals) -------------------------
__device__ float g_h[(size_t)P4 * 128];     // LN1+pw1 out, NHWC
__device__ float g_v[(size_t)P4 * 128];     // value proj
__device__ float g_dw[(size_t)P4 * 128];    // depthwise conv out
__device__ float g_om[(size_t)P4 * 112];    // offset/mask proj (first 108 used)
__device__ float g_f[(size_t)P4 * 64];      // gated branch features
__device__ float g_y[(size_t)P2 * 128];     // [y_l(64) ; y_r(64)] NHWC per batch
__device__ float g_zg[(size_t)P2 * 64];     // gated conv4 output
__device__ float g_part[64 * 64];           // pooling partials [img*16+seg][64]
__device__ float g_s[256];                  // SCA scale s[b][128]

// ------------------------- tf32 mma helpers -------------------------
__device__ __forceinline__ uint32_t f2tf32(float f) {
    uint32_t r;
    asm("cvt.rna.tf32.f32 %0, %1;" : "=r"(r) : "f"(f));
    return r;
}
__device__ __forceinline__ void mma_tf32(float* c, const uint32_t* a, const uint32_t* b) {
    asm volatile(
        "mma.sync.aligned.m16n8k8.row.col.f32.tf32.tf32.f32 "
        "{%0,%1,%2,%3}, {%4,%5,%6,%7}, {%8,%9}, {%0,%1,%2,%3};"
        : "+f"(c[0]), "+f"(c[1]), "+f"(c[2]), "+f"(c[3])
        : "r"(a[0]), "r"(a[1]), "r"(a[2]), "r"(a[3]), "r"(b[0]), "r"(b[1]));
}

// ------------------------- kernel 1: LN(64ch) + pw1 (64 -> 128) -------------------------
__global__ void __launch_bounds__(256) k_ln_pw1(const float* __restrict__ x_l,
                                                const float* __restrict__ x_r,
                                                const float* __restrict__ g1,
                                                const float* __restrict__ W,
                                                const float* __restrict__ Bb) {
    extern __shared__ float sm[];
    float* Xs = sm;                  // 64 px * 68
    float* Ws = sm + 64 * 68;        // 128*64
    float* mr = Ws + 128 * 64;       // 128
    int tid = threadIdx.x;
    int base = blockIdx.x * 64;
    int img = base / HW;
    int pos = base - img * HW;
    const float* xp = (img < 2) ? (x_l + (size_t)img * HW * 64)
                                : (x_r + (size_t)(img - 2) * HW * 64);
    for (int i = tid; i < 64 * 64; i += 256) {
        int c = i >> 6, p = i & 63;
        Xs[p * 68 + c] = xp[(size_t)c * HW + pos + p];
    }
    for (int i = tid; i < 128 * 64; i += 256) Ws[i] = W[i];
    __syncthreads();
    if (tid < 64) {
        float s = 0.f, sq = 0.f;
        for (int c = 0; c < 64; c++) { float v = Xs[tid * 68 + c]; s += v; sq += v * v; }
        float m = s * (1.f / 64.f);
        float var = sq * (1.f / 64.f) - m * m;
        mr[tid] = m; mr[64 + tid] = rsqrtf(var + 1e-5f);
    }
    __syncthreads();
    for (int i = tid; i < 64 * 64; i += 256) {
        int p = i >> 6, c = i & 63;
        Xs[p * 68 + c] = (Xs[p * 68 + c] - mr[p]) * mr[64 + p] * __ldg(&g1[c]);
    }
    __syncthreads();
    int pr = tid & 15, og = tid >> 4;
    float acc[4][8];
#pragma unroll
    for (int j = 0; j < 8; j++) {
        float b = Bb[og * 8 + j];
#pragma unroll
        for (int i = 0; i < 4; i++) acc[i][j] = b;
    }
#pragma unroll 4
    for (int k = 0; k < 64; k += 4) {
        float4 xv[4];
#pragma unroll
        for (int i = 0; i < 4; i++) xv[i] = *(const float4*)&Xs[(pr + 16 * i) * 68 + k];
#pragma unroll
        for (int j = 0; j < 8; j++) {
            float4 wv = *(const float4*)&Ws[(og * 8 + j) * 64 + k];
#pragma unroll
            for (int i = 0; i < 4; i++)
                acc[i][j] += xv[i].x * wv.x + xv[i].y * wv.y + xv[i].z * wv.z + xv[i].w * wv.w;
        }
    }
#pragma unroll
    for (int i = 0; i < 4; i++)
#pragma unroll
        for (int j = 0; j < 8; j++)
            g_h[(size_t)(base + pr + 16 * i) * 128 + og * 8 + j] = acc[i][j];
}

// ------------------------- tf32 tensor-core GEMM: 128px x N, K=128 -------------------------
// Block 256 thr = 8 warps (4 m-warps x 2 n-warps); warp tile 32px x 64out.
template <int N>
__global__ void __launch_bounds__(256) k_tgemm(const float* __restrict__ X,
                                               float* __restrict__ Y,
                                               const float* __restrict__ W,
                                               const float* __restrict__ Bb) {
    extern __shared__ float sm[];
    float* Xs = sm;                 // 128 x 132 (tf32 bit patterns)
    float* Ws = sm + 128 * 132;     // 128 x 132 (rows >= N zeroed)
    const uint32_t* Xu = (const uint32_t*)Xs;
    const uint32_t* Wu = (const uint32_t*)Ws;
    int tid = threadIdx.x;
    size_t base = (size_t)blockIdx.x * 128;

    for (int i = tid; i < 128 * 32; i += 256) {
        int row = i >> 5, q = i & 31;
        float4 v = *(const float4*)&X[(base + row) * 128 + q * 4];
        uint32_t* d = (uint32_t*)&Xs[row * 132 + q * 4];
        d[0] = f2tf32(v.x); d[1] = f2tf32(v.y); d[2] = f2tf32(v.z); d[3] = f2tf32(v.w);
    }
    for (int i = tid; i < 128 * 32; i += 256) {
        int row = i >> 5, q = i & 31;
        uint32_t* d = (uint32_t*)&Ws[row * 132 + q * 4];
        if (row < N) {
            float4 v = *(const float4*)&W[row * 128 + q * 4];
            d[0] = f2tf32(v.x); d[1] = f2tf32(v.y); d[2] = f2tf32(v.z); d[3] = f2tf32(v.w);
        } else {
            d[0] = 0u; d[1] = 0u; d[2] = 0u; d[3] = 0u;
        }
    }
    __syncthreads();

    int wid = tid >> 5, lane = tid & 31;
    int wm = wid & 3, wn = wid >> 2;
    int gid = lane >> 2, tig = lane & 3;

    float c[2][8][4];
#pragma unroll
    for (int nt = 0; nt < 8; nt++) {
        int o = wn * 64 + nt * 8 + 2 * tig;
        float b0 = (o < N) ? Bb[o] : 0.f;
        float b1 = (o + 1 < N) ? Bb[o + 1] : 0.f;
#pragma unroll
        for (int mt = 0; mt < 2; mt++) {
            c[mt][nt][0] = b0; c[mt][nt][1] = b1;
            c[mt][nt][2] = b0; c[mt][nt][3] = b1;
        }
    }

#pragma unroll 4
    for (int k0 = 0; k0 < 128; k0 += 8) {
        uint32_t A[2][4];
#pragma unroll
        for (int mt = 0; mt < 2; mt++) {
            int r = wm * 32 + mt * 16 + gid;
            A[mt][0] = Xu[r * 132 + k0 + tig];
            A[mt][1] = Xu[(r + 8) * 132 + k0 + tig];
            A[mt][2] = Xu[r * 132 + k0 + tig + 4];
            A[mt][3] = Xu[(r + 8) * 132 + k0 + tig + 4];
        }
        uint32_t Bf[8][2];
#pragma unroll
        for (int nt = 0; nt < 8; nt++) {
            int n = wn * 64 + nt * 8 + gid;
            Bf[nt][0] = Wu[n * 132 + k0 + tig];
            Bf[nt][1] = Wu[n * 132 + k0 + tig + 4];
        }
#pragma unroll
        for (int mt = 0; mt < 2; mt++)
#pragma unroll
            for (int nt = 0; nt < 8; nt++)
                mma_tf32(c[mt][nt], A[mt], Bf[nt]);
    }

#pragma unroll
    for (int mt = 0; mt < 2; mt++) {
        size_t r0 = base + wm * 32 + mt * 16 + gid;
#pragma unroll
        for (int nt = 0; nt < 8; nt++) {
            int o = wn * 64 + nt * 8 + 2 * tig;
            if (o < N) {
                *(float2*)&Y[r0 * N + o] = make_float2(c[mt][nt][0], c[mt][nt][1]);
                *(float2*)&Y[(r0 + 8) * N + o] = make_float2(c[mt][nt][2], c[mt][nt][3]);
            }
        }
    }
}

// ------------------------- depthwise 3x3, 4 px per thread -------------------------
__global__ void __launch_bounds__(256) k_dwc4(const float* __restrict__ Wd,
                                              const float* __restrict__ Bd) {
    int linear = blockIdx.x * 256 + threadIdx.x;
    int c = linear & 127;
    int pq = linear >> 7;            // quad index
    int img = pq / 6400;
    int q = pq - img * 6400;
    int h = q / 40;
    int w4 = (q - h * 40) * 4;
    float wt[9];
#pragma unroll
    for (int t = 0; t < 9; t++) wt[t] = __ldg(&Wd[t * 128 + c]);
    float a[4];
    float bv = __ldg(&Bd[c]);
#pragma unroll
    for (int j = 0; j < 4; j++) a[j] = bv;
    const float* basep = g_h + (size_t)img * HW * 128 + c;
#pragma unroll
    for (int dy = 0; dy < 3; dy++) {
        int y = h + dy - 1;
        if ((unsigned)y >= 160u) continue;
        const float* row = basep + (size_t)y * 160 * 128;
#pragma unroll
        for (int t = 0; t < 6; t++) {
            int x = w4 + t - 1;
            if ((unsigned)x >= 160u) continue;
            float v = __ldg(&row[(size_t)x * 128]);
#pragma unroll
            for (int j = 0; j < 4; j++) {
                int dx = t - j;
                if (dx >= 0 && dx <= 2) a[j] += v * wt[dy * 3 + dx];
            }
        }
    }
    size_t o = ((size_t)pq * 4) * 128 + c;
#pragma unroll
    for (int j = 0; j < 4; j++) g_dw[o + (size_t)j * 128] = a[j];
}

// ------------------------- fused: deformable sample + outp GEMM + SimpleGate -------------------------
__device__ __forceinline__ void fma4(float4& a, float w, const float4 v) {
    a.x += w * v.x; a.y += w * v.y; a.z += w * v.z; a.w += w * v.w;
}

__global__ void __launch_bounds__(256) k_souter(const float* __restrict__ Wo,
                                                const float* __restrict__ Bo) {
    extern __shared__ float sm[];
    float* Ws = sm;                   // 128*128
    float* Xs = sm + 16384;           // 64*132 sampled features
    float* OMs = Xs + 64 * 132;       // 8 warps * 112
    int tid = threadIdx.x;
    int base = blockIdx.x * 64;
    int img = base / HW;
    int pbase = base - img * HW;
    for (int i = tid; i < 16384; i += 256) Ws[i] = Wo[i];
    int wrp = tid >> 5, lane = tid & 31;
    int g = lane >> 3, c4 = lane & 7;
    const float* vg = g_v + (size_t)img * HW * 128 + g * 32 + c4 * 4;
    float* oms = OMs + wrp * 112;
    for (int p8 = 0; p8 < 8; p8++) {
        int px = wrp * 8 + p8;
        int pos = pbase + px;
        int hh = pos / 160, ww = pos - hh * 160;
        const float* omp = g_om + ((size_t)img * HW + pos) * 112;
        __syncwarp();
        oms[lane] = omp[lane];
        oms[32 + lane] = omp[32 + lane];
        oms[64 + lane] = omp[64 + lane];
        if (lane < 12) oms[96 + lane] = omp[96 + lane];
        __syncwarp();
        float4 acc = make_float4(0.f, 0.f, 0.f, 0.f);
#pragma unroll
        for (int k = 0; k < 9; k++) {
            float ox = oms[g * 27 + k * 3 + 0];
            float oy = oms[g * 27 + k * 3 + 1];
            float mk = oms[g * 27 + k * 3 + 2];
            float fx = (float)(ww + (k % 3) - 1) + ox;
            float fy = (float)(hh + (k / 3) - 1) + oy;
            float x0f = floorf(fx), y0f = floorf(fy);
            float tx = fx - x0f, ty = fy - y0f;
            int ix = (int)x0f, iy = (int)y0f;
            float w00 = (1.f - tx) * (1.f - ty) * mk;
            float w01 = tx * (1.f - ty) * mk;
            float w10 = (1.f - tx) * ty * mk;
            float w11 = tx * ty * mk;
            if ((unsigned)iy < 160u) {
                if ((unsigned)ix < 160u)
                    fma4(acc, w00, *(const float4*)&vg[(size_t)(iy * 160 + ix) * 128]);
                if ((unsigned)(ix + 1) < 160u)
                    fma4(acc, w01, *(const float4*)&vg[(size_t)(iy * 160 + ix + 1) * 128]);
            }
            if ((unsigned)(iy + 1) < 160u) {
                if ((unsigned)ix < 160u)
                    fma4(acc, w10, *(const float4*)&vg[(size_t)((iy + 1) * 160 + ix) * 128]);
                if ((unsigned)(ix + 1) < 160u)
                    fma4(acc, w11, *(const float4*)&vg[(size_t)((iy + 1) * 160 + ix + 1) * 128]);
            }
        }
        *(float4*)&Xs[px * 132 + lane * 4] = acc;
    }
    __syncthreads();
    int pr = tid & 15, og = tid >> 4;
    float aA[4][4], aB[4][4];
#pragma unroll
    for (int j = 0; j < 4; j++) {
        float ba = Bo[og * 4 + j], bb = Bo[og * 4 + j + 64];
#pragma unroll
        for (int i = 0; i < 4; i++) { aA[i][j] = ba; aB[i][j] = bb; }
    }
#pragma unroll 4
    for (int k = 0; k < 128; k += 4) {
        float4 xv[4];
#pragma unroll
        for (int i = 0; i < 4; i++) xv[i] = *(const float4*)&Xs[(pr + 16 * i) * 132 + k];
#pragma unroll
        for (int j = 0; j < 4; j++) {
            float4 wa = *(const float4*)&Ws[(og * 4 + j) * 128 + k];
            float4 wb = *(const float4*)&Ws[(og * 4 + j + 64) * 128 + k];
#pragma unroll
            for (int i = 0; i < 4; i++) {
                aA[i][j] += xv[i].x * wa.x + xv[i].y * wa.y + xv[i].z * wa.z + xv[i].w * wa.w;
                aB[i][j] += xv[i].x * wb.x + xv[i].y * wb.y + xv[i].z * wb.z + xv[i].w * wb.w;
            }
        }
    }
#pragma unroll
    for (int i = 0; i < 4; i++)
#pragma unroll
        for (int j = 0; j < 4; j++)
            g_f[(size_t)(base + pr + 16 * i) * 64 + og * 4 + j] = aA[i][j] * aB[i][j];
}

// ------------------------- pooling partials -------------------------
__global__ void __launch_bounds__(256) k_pool() {
    __shared__ float sh[256];
    int img = blockIdx.x >> 4, seg = blockIdx.x & 15;
    int tid = threadIdx.x;
    int c = tid & 63, q = tid >> 6;
    const float* fp = g_f + ((size_t)img * HW + seg * 1600) * 64;
    float s = 0.f;
    for (int n = 0; n < 400; n++) s += fp[(size_t)(q + 4 * n) * 64 + c];
    sh[tid] = s;
    __syncthreads();
    if (tid < 64)
        g_part[(img * 16 + seg) * 64 + tid] = sh[tid] + sh[tid + 64] + sh[tid + 128] + sh[tid + 192];
}

// ------------------------- finish pooling + SCA projection -------------------------
__global__ void __launch_bounds__(256) k_sca(const float* __restrict__ sw, const float* __restrict__ sb) {
    __shared__ float shp[256];
    int tid = threadIdx.x;
    int b = tid >> 7, c = tid & 127;
    int img = (c < 64) ? b : (2 + b);
    int cc = c & 63;
    float s = 0.f;
    for (int seg = 0; seg < 16; seg++) s += g_part[(img * 16 + seg) * 64 + cc];
    shp[tid] = s * (1.f / (float)HW);
    __syncthreads();
    float acc = __ldg(&sb[c]);
    for (int k = 0; k < 128; k++) acc += shp[b * 128 + k] * __ldg(&sw[c * 128 + k]);
    g_s[tid] = acc;
}

// ------------------------- SCA-folded conv3 + dual residual -> g_y -------------------------
__global__ void __launch_bounds__(256) k_conv3_y(const float* __restrict__ W3,
                                                 const float* __restrict__ B3,
                                                 const float* __restrict__ beta,
                                                 const float* __restrict__ x_l,
                                                 const float* __restrict__ x_r) {
    extern __shared__ float sm[];
    float* Fs = sm;              // 64*132
    float* W3s = sm + 64 * 132;  // 64*128 (scale-folded)
    int tid = threadIdx.x;
    int base = blockIdx.x * 64;
    int b = base / HW;
    int pos = base - b * HW;
    for (int i = tid; i < 64 * 128; i += 256) {
        int p = i >> 7, o = i & 127;
        float v = (o < 64) ? g_f[((size_t)b * HW + pos + p) * 64 + o]
                           : g_f[((size_t)(2 + b) * HW + pos + p) * 64 + (o - 64)];
        Fs[p * 132 + o] = v;
    }
    for (int i = tid; i < 64 * 128; i += 256) {
        int o = i & 127;
        W3s[i] = W3[i] * g_s[b * 128 + o];
    }
    __syncthreads();
    int pr = tid & 15, og = tid >> 4;
    float acc[4][4];
#pragma unroll
    for (int j = 0; j < 4; j++) {
        float bv = B3[og * 4 + j];
#pragma unroll
        for (int i = 0; i < 4; i++) acc[i][j] = bv;
    }
#pragma unroll 4
    for (int k = 0; k < 128; k += 4) {
        float4 xv[4];
#pragma unroll
        for (int i = 0; i < 4; i++) xv[i] = *(const float4*)&Fs[(pr + 16 * i) * 132 + k];
#pragma unroll
        for (int j = 0; j < 4; j++) {
            float4 wv = *(const float4*)&W3s[(og * 4 + j) * 128 + k];
#pragma unroll
            for (int i = 0; i < 4; i++)
                acc[i][j] += xv[i].x * wv.x + xv[i].y * wv.y + xv[i].z * wv.z + xv[i].w * wv.w;
        }
    }
#pragma unroll
    for (int i = 0; i < 4; i++) {
        int p = pr + 16 * i;
#pragma unroll
        for (int j = 0; j < 4; j++) {
            int jj = og * 4 + j;
            float bt = __ldg(&beta[jj]);
            float x3 = acc[i][j] * bt;
            float xl = x_l[((size_t)b * 64 + jj) * HW + pos + p];
            float xr = x_r[((size_t)b * 64 + jj) * HW + pos + p];
            g_y[(size_t)(base + p) * 128 + jj] = xl + x3;
            g_y[(size_t)(base + p) * 128 + 64 + jj] = xr + x3;
        }
    }
}

// ------------------------- LN2(128ch) + conv4 + gate -> g_zg -------------------------
__global__ void __launch_bounds__(256) k_ln2c4(const float* __restrict__ g2,
                                               const float* __restrict__ W4,
                                               const float* __restrict__ B4) {
    extern __shared__ float sm[];
    float* Ys = sm;               // 64*132
    float* Ws = sm + 64 * 132;    // 128*128
    float* mr = Ws + 128 * 128;   // 128
    int tid = threadIdx.x;
    int base = blockIdx.x * 64;
    for (int i = tid; i < 64 * 128; i += 256) {
        int p = i >> 7, c = i & 127;
        Ys[p * 132 + c] = g_y[(size_t)(base + p) * 128 + c];
    }
    for (int i = tid; i < 128 * 128; i += 256) Ws[i] = W4[i];
    __syncthreads();
    if (tid < 64) {
        float s = 0.f, sq = 0.f;
        for (int c = 0; c < 128; c++) { float v = Ys[tid * 132 + c]; s += v; sq += v * v; }
        float m = s * (1.f / 128.f);
        float var = sq * (1.f / 128.f) - m * m;
        mr[tid] = m; mr[64 + tid] = rsqrtf(var + 1e-5f);
    }
    __syncthreads();
    for (int i = tid; i < 64 * 128; i += 256) {
        int p = i >> 7, c = i & 127;
        Ys[p * 132 + c] = (Ys[p * 132 + c] - mr[p]) * mr[64 + p] * __ldg(&g2[c]);
    }
    __syncthreads();
    int pr = tid & 15, og = tid >> 4;
    float aA[4][4], aB[4][4];
#pragma unroll
    for (int j = 0; j < 4; j++) {
        float ba = B4[og * 4 + j], bb = B4[og * 4 + j + 64];
#pragma unroll
        for (int i = 0; i < 4; i++) { aA[i][j] = ba; aB[i][j] = bb; }
    }
#pragma unroll 4
    for (int k = 0; k < 128; k += 4) {
        float4 xv[4];
#pragma unroll
        for (int i = 0; i < 4; i++) xv[i] = *(const float4*)&Ys[(pr + 16 * i) * 132 + k];
#pragma unroll
        for (int j = 0; j < 4; j++) {
            float4 wa = *(const float4*)&Ws[(og * 4 + j) * 128 + k];
            float4 wb = *(const float4*)&Ws[(og * 4 + j + 64) * 128 + k];
#pragma unroll
            for (int i = 0; i < 4; i++) {
                aA[i][j] += xv[i].x * wa.x + xv[i].y * wa.y + xv[i].z * wa.z + xv[i].w * wa.w;
                aB[i][j] += xv[i].x * wb.x + xv[i].y * wb.y + xv[i].z * wb.z + xv[i].w * wb.w;
            }
        }
    }
#pragma unroll
    for (int i = 0; i < 4; i++)
#pragma unroll
        for (int j = 0; j < 4; j++)
            g_zg[(size_t)(base + pr + 16 * i) * 64 + og * 4 + j] = aA[i][j] * aB[i][j];
}

// ------------------------- conv5 + final residuals, NCHW outputs -------------------------
__global__ void __launch_bounds__(256) k_c5out(const float* __restrict__ W5,
                                               const float* __restrict__ B5,
                                               const float* __restrict__ gamma,
                                               float* __restrict__ out) {
    extern __shared__ float sm[];
    float* Zs = sm;                    // 64*68
    float* W5s = sm + 64 * 68;         // 64*64
    float* Ys = W5s + 64 * 64;         // 64*132
    int tid = threadIdx.x;
    int base = blockIdx.x * 64;
    int b = base / HW;
    int pos = base - b * HW;
    for (int i = tid; i < 64 * 64; i += 256) {
        int p = i >> 6, k = i & 63;
        Zs[p * 68 + k] = g_zg[(size_t)(base + p) * 64 + k];
    }
    for (int i = tid; i < 64 * 64; i += 256) W5s[i] = W5[i];
    for (int i = tid; i < 64 * 128; i += 256) {
        int p = i >> 7, c = i & 127;
        Ys[p * 132 + c] = g_y[(size_t)(base + p) * 128 + c];
    }
    __syncthreads();
    int pr = tid & 15, og = tid >> 4;
    float acc[4][4];
#pragma unroll
    for (int j = 0; j < 4; j++) {
        float bv = B5[og * 4 + j];
#pragma unroll
        for (int i = 0; i < 4; i++) acc[i][j] = bv;
    }
#pragma unroll 4
    for (int k = 0; k < 64; k += 4) {
        float4 xv[4];
#pragma unroll
        for (int i = 0; i < 4; i++) xv[i] = *(const float4*)&Zs[(pr + 16 * i) * 68 + k];
#pragma unroll
        for (int j = 0; j < 4; j++) {
            float4 wv = *(const float4*)&W5s[(og * 4 + j) * 64 + k];
#pragma unroll
            for (int i = 0; i < 4; i++)
                acc[i][j] += xv[i].x * wv.x + xv[i].y * wv.y + xv[i].z * wv.z + xv[i].w * wv.w;
        }
    }
    const size_t HALF = (size_t)2 * 64 * HW;
#pragma unroll
    for (int i = 0; i < 4; i++) {
        int p = pr + 16 * i;
#pragma unroll
        for (int j = 0; j < 4; j++) {
            int cc = og * 4 + j;
            float z = acc[i][j] * __ldg(&gamma[cc]);
            size_t o = ((size_t)b * 64 + cc) * HW + pos + p;
            out[o] = Ys[p * 132 + cc] + z;
            out[HALF + o] = Ys[p * 132 + 64 + cc] + z;
        }
    }
}

// ------------------------- host -------------------------
extern "C" void kernel_launch(void* const* d_in, const int* in_sizes, int n_in,
                              void* d_out, int out_size) {
    const float* x_l     = (const float*)d_in[0];
    const float* x_r     = (const float*)d_in[1];
    const float* ln1_g   = (const float*)d_in[2];
    const float* pw1_w   = (const float*)d_in[3];
    const float* pw1_b   = (const float*)d_in[4];
    const float* val_w   = (const float*)d_in[5];
    const float* val_b   = (const float*)d_in[6];
    const float* dwc_w   = (const float*)d_in[7];
    const float* dwc_b   = (const float*)d_in[8];
    const float* om_w    = (const float*)d_in[9];
    const float* om_b    = (const float*)d_in[10];
    const float* outp_w  = (const float*)d_in[11];
    const float* outp_b  = (const float*)d_in[12];
    const float* sca_w   = (const float*)d_in[13];
    const float* sca_b   = (const float*)d_in[14];
    const float* conv3_w = (const float*)d_in[15];
    const float* conv3_b = (const float*)d_in[16];
    const float* norm2_g = (const float*)d_in[17];
    const float* conv4_w = (const float*)d_in[18];
    const float* conv4_b = (const float*)d_in[19];
    const float* conv5_w = (const float*)d_in[20];
    const float* conv5_b = (const float*)d_in[21];
    const float* beta    = (const float*)d_in[22];
    const float* gamma   = (const float*)d_in[23];
    float* out = (float*)d_out;

    float *ph, *pv, *pdw, *pom;
    cudaGetSymbolAddress((void**)&ph, g_h);
    cudaGetSymbolAddress((void**)&pv, g_v);
    cudaGetSymbolAddress((void**)&pdw, g_dw);
    cudaGetSymbolAddress((void**)&pom, g_om);

    const int SM_LNPW1 = (64 * 68 + 128 * 64 + 128) * 4;
    const int SM_TG    = (2 * 128 * 132) * 4;                       // 135168
    const int SM_SOUT  = (128 * 128 + 64 * 132 + 8 * 112) * 4;
    const int SM_C3    = (64 * 132 + 64 * 128) * 4;
    const int SM_LN2   = (64 * 132 + 128 * 128 + 128) * 4;
    const int SM_C5    = (64 * 68 + 64 * 64 + 64 * 132) * 4;

    cudaFuncSetAttribute(k_ln_pw1,     cudaFuncAttributeMaxDynamicSharedMemorySize, SM_LNPW1);
    cudaFuncSetAttribute(k_tgemm<128>, cudaFuncAttributeMaxDynamicSharedMemorySize, SM_TG);
    cudaFuncSetAttribute(k_tgemm<112>, cudaFuncAttributeMaxDynamicSharedMemorySize, SM_TG);
    cudaFuncSetAttribute(k_souter,     cudaFuncAttributeMaxDynamicSharedMemorySize, SM_SOUT);
    cudaFuncSetAttribute(k_conv3_y,    cudaFuncAttributeMaxDynamicSharedMemorySize, SM_C3);
    cudaFuncSetAttribute(k_ln2c4,      cudaFuncAttributeMaxDynamicSharedMemorySize, SM_LN2);
    cudaFuncSetAttribute(k_c5out,      cudaFuncAttributeMaxDynamicSharedMemorySize, SM_C5);

    k_ln_pw1     <<<P4 / 64, 256, SM_LNPW1>>>(x_l, x_r, ln1_g, pw1_w, pw1_b);
    k_tgemm<128> <<<P4 / 128, 256, SM_TG>>>(ph, pv, val_w, val_b);       // value proj
    k_dwc4       <<<P4 * 128 / (256 * 4), 256>>>(dwc_w, dwc_b);
    k_tgemm<112> <<<P4 / 128, 256, SM_TG>>>(pdw, pom, om_w, om_b);       // offset/mask proj
    k_souter     <<<P4 / 64, 256, SM_SOUT>>>(outp_w, outp_b);
    k_pool       <<<64, 256>>>();
    k_sca        <<<1, 256>>>(sca_w, sca_b);
    k_conv3_y    <<<P2 / 64, 256, SM_C3>>>(conv3_w, conv3_b, beta, x_l, x_r);
    k_ln2c4      <<<P2 / 64, 256, SM_LN2>>>(norm2_g, conv4_w, conv4_b);
    k_c5out      <<<P2 / 64, 256, SM_C5>>>(conv5_w, conv5_b, gamma, out);
}

// round 5
// speedup vs baseline: 2.2298x; 1.8721x over previous
#include <cuda_runtime.h>
#include <cuda_bf16.h>
#include <cstdint>

#define HW 25600
#define P4 102400   // 4 images * HW  (img 0,1 = x_l b0,b1 ; img 2,3 = x_r b0,b1)
#define P2 51200    // 2 batches * HW

// ------------------------- scratch (__device__ globals) -------------------------
__device__ float g_h[(size_t)P4 * 128];     // LN1+pw1 out, NHWC
__device__ float g_v[(size_t)P4 * 128];     // value proj
__device__ float g_dw[(size_t)P4 * 128];    // depthwise conv out
__device__ float g_om[(size_t)P4 * 112];    // offset/mask proj (first 108 used)
__device__ float g_f[(size_t)P4 * 64];      // gated branch features
__device__ float g_y[(size_t)P2 * 128];     // [y_l(64) ; y_r(64)] NHWC per batch
__device__ float g_zg[(size_t)P2 * 64];     // gated conv4 output
__device__ float g_part[64 * 64];           // pooling partials [img*16+seg][64]
__device__ float g_s[256];                  // SCA scale s[b][128]

// ------------------------- bf16 mma helpers -------------------------
__device__ __forceinline__ uint32_t pk(float a, float b) {
    __nv_bfloat162 t = __floats2bfloat162_rn(a, b);
    return *reinterpret_cast<uint32_t*>(&t);
}
__device__ __forceinline__ void mma_bf16(float* c, const uint32_t* a, const uint32_t* b) {
    asm volatile(
        "mma.sync.aligned.m16n8k16.row.col.f32.bf16.bf16.f32 "
        "{%0,%1,%2,%3}, {%4,%5,%6,%7}, {%8,%9}, {%0,%1,%2,%3};"
        : "+f"(c[0]), "+f"(c[1]), "+f"(c[2]), "+f"(c[3])
        : "r"(a[0]), "r"(a[1]), "r"(a[2]), "r"(a[3]), "r"(b[0]), "r"(b[1]));
}

// ------------------------- kernel 1: LN(64ch) + pw1 (64 -> 128), bf16 mma -------------------------
__global__ void __launch_bounds__(256) k_ln_pw1(const float* __restrict__ x_l,
                                                const float* __restrict__ x_r,
                                                const float* __restrict__ g1,
                                                const float* __restrict__ W,
                                                const float* __restrict__ Bb) {
    extern __shared__ float sm[];
    float* Xf = sm;                            // 64*68 fp32
    uint32_t* Xb = (uint32_t*)(sm + 64 * 68);  // 64*36 words (bf16 pairs, K=64)
    uint32_t* Wb = Xb + 64 * 36;               // 128*36 words
    float* mr = (float*)(Wb + 128 * 36);       // 128
    int tid = threadIdx.x;
    int base = blockIdx.x * 64;
    int img = base / HW;
    int pos = base - img * HW;
    const float* xp = (img < 2) ? (x_l + (size_t)img * HW * 64)
                                : (x_r + (size_t)(img - 2) * HW * 64);
    for (int i = tid; i < 64 * 64; i += 256) {
        int c = i >> 6, p = i & 63;
        Xf[p * 68 + c] = xp[(size_t)c * HW + pos + p];
    }
    for (int i = tid; i < 128 * 16; i += 256) {
        int row = i >> 4, q = i & 15;
        float4 v = *(const float4*)&W[row * 64 + q * 4];
        Wb[row * 36 + q * 2] = pk(v.x, v.y);
        Wb[row * 36 + q * 2 + 1] = pk(v.z, v.w);
    }
    __syncthreads();
    if (tid < 64) {
        float s = 0.f, sq = 0.f;
        for (int c = 0; c < 64; c++) { float v = Xf[tid * 68 + c]; s += v; sq += v * v; }
        float m = s * (1.f / 64.f);
        float var = sq * (1.f / 64.f) - m * m;
        mr[tid] = m; mr[64 + tid] = rsqrtf(var + 1e-5f);
    }
    __syncthreads();
    for (int i = tid; i < 64 * 32; i += 256) {
        int p = i >> 5, q = i & 31;
        int k0 = q * 2;
        float f0 = (Xf[p * 68 + k0] - mr[p]) * mr[64 + p] * __ldg(&g1[k0]);
        float f1 = (Xf[p * 68 + k0 + 1] - mr[p]) * mr[64 + p] * __ldg(&g1[k0 + 1]);
        Xb[p * 36 + q] = pk(f0, f1);
    }
    __syncthreads();
    int wid = tid >> 5, lane = tid & 31;
    int wm = wid & 1, wn = wid >> 1;      // 2 m-warps x 4 n-warps (32 cols each)
    int gid = lane >> 2, tig = lane & 3;
    float c[2][4][4];
#pragma unroll
    for (int nt = 0; nt < 4; nt++) {
        int o = wn * 32 + nt * 8 + 2 * tig;
        float b0 = Bb[o], b1 = Bb[o + 1];
#pragma unroll
        for (int mt = 0; mt < 2; mt++) {
            c[mt][nt][0] = b0; c[mt][nt][1] = b1;
            c[mt][nt][2] = b0; c[mt][nt][3] = b1;
        }
    }
#pragma unroll
    for (int kw = 0; kw < 32; kw += 8) {
        uint32_t A[2][4];
#pragma unroll
        for (int mt = 0; mt < 2; mt++) {
            int r = wm * 32 + mt * 16 + gid;
            A[mt][0] = Xb[r * 36 + kw + tig];
            A[mt][1] = Xb[(r + 8) * 36 + kw + tig];
            A[mt][2] = Xb[r * 36 + kw + 4 + tig];
            A[mt][3] = Xb[(r + 8) * 36 + kw + 4 + tig];
        }
#pragma unroll
        for (int nt = 0; nt < 4; nt++) {
            int n = wn * 32 + nt * 8 + gid;
            uint32_t Bf[2];
            Bf[0] = Wb[n * 36 + kw + tig];
            Bf[1] = Wb[n * 36 + kw + 4 + tig];
#pragma unroll
            for (int mt = 0; mt < 2; mt++) mma_bf16(c[mt][nt], A[mt], Bf);
        }
    }
#pragma unroll
    for (int mt = 0; mt < 2; mt++) {
        size_t r0 = base + wm * 32 + mt * 16 + gid;
#pragma unroll
        for (int nt = 0; nt < 4; nt++) {
            int o = wn * 32 + nt * 8 + 2 * tig;
            *(float2*)&g_h[r0 * 128 + o] = make_float2(c[mt][nt][0], c[mt][nt][1]);
            *(float2*)&g_h[(r0 + 8) * 128 + o] = make_float2(c[mt][nt][2], c[mt][nt][3]);
        }
    }
}

// ------------------------- bf16 tensor GEMM: 128px x N, K=128 -------------------------
template <int N>
__global__ void __launch_bounds__(256) k_tg(const float* __restrict__ X,
                                            float* __restrict__ Y,
                                            const float* __restrict__ W,
                                            const float* __restrict__ Bb) {
    extern __shared__ uint32_t smu[];
    uint32_t* Xu = smu;              // 128*68 words
    uint32_t* Wu = smu + 128 * 68;   // 128*68 words (rows >= N zeroed)
    int tid = threadIdx.x;
    size_t base = (size_t)blockIdx.x * 128;
    for (int i = tid; i < 4096; i += 256) {
        int row = i >> 5, q = i & 31;
        float4 v = *(const float4*)&X[(base + row) * 128 + q * 4];
        Xu[row * 68 + q * 2] = pk(v.x, v.y);
        Xu[row * 68 + q * 2 + 1] = pk(v.z, v.w);
    }
    for (int i = tid; i < 4096; i += 256) {
        int row = i >> 5, q = i & 31;
        uint32_t lo = 0u, hi = 0u;
        if (row < N) {
            float4 v = *(const float4*)&W[row * 128 + q * 4];
            lo = pk(v.x, v.y); hi = pk(v.z, v.w);
        }
        Wu[row * 68 + q * 2] = lo;
        Wu[row * 68 + q * 2 + 1] = hi;
    }
    __syncthreads();
    int wid = tid >> 5, lane = tid & 31;
    int wm = wid & 3, wn = wid >> 2;     // 4 m-warps x 2 n-warps (64 cols each)
    int gid = lane >> 2, tig = lane & 3;
    float c[2][8][4];
#pragma unroll
    for (int nt = 0; nt < 8; nt++) {
        int o = wn * 64 + nt * 8 + 2 * tig;
        float b0 = (o < N) ? Bb[o] : 0.f;
        float b1 = (o + 1 < N) ? Bb[o + 1] : 0.f;
#pragma unroll
        for (int mt = 0; mt < 2; mt++) {
            c[mt][nt][0] = b0; c[mt][nt][1] = b1;
            c[mt][nt][2] = b0; c[mt][nt][3] = b1;
        }
    }
#pragma unroll
    for (int kw = 0; kw < 64; kw += 8) {
        uint32_t A[2][4];
#pragma unroll
        for (int mt = 0; mt < 2; mt++) {
            int r = wm * 32 + mt * 16 + gid;
            A[mt][0] = Xu[r * 68 + kw + tig];
            A[mt][1] = Xu[(r + 8) * 68 + kw + tig];
            A[mt][2] = Xu[r * 68 + kw + 4 + tig];
            A[mt][3] = Xu[(r + 8) * 68 + kw + 4 + tig];
        }
        uint32_t Bf[8][2];
#pragma unroll
        for (int nt = 0; nt < 8; nt++) {
            int n = wn * 64 + nt * 8 + gid;
            Bf[nt][0] = Wu[n * 68 + kw + tig];
            Bf[nt][1] = Wu[n * 68 + kw + 4 + tig];
        }
#pragma unroll
        for (int mt = 0; mt < 2; mt++)
#pragma unroll
            for (int nt = 0; nt < 8; nt++)
                mma_bf16(c[mt][nt], A[mt], Bf[nt]);
    }
#pragma unroll
    for (int mt = 0; mt < 2; mt++) {
        size_t r0 = base + wm * 32 + mt * 16 + gid;
#pragma unroll
        for (int nt = 0; nt < 8; nt++) {
            int o = wn * 64 + nt * 8 + 2 * tig;
            if (o < N) {
                *(float2*)&Y[r0 * N + o] = make_float2(c[mt][nt][0], c[mt][nt][1]);
                *(float2*)&Y[(r0 + 8) * N + o] = make_float2(c[mt][nt][2], c[mt][nt][3]);
            }
        }
    }
}

// ------------------------- depthwise 3x3, 4 px per thread -------------------------
__global__ void __launch_bounds__(256) k_dwc4(const float* __restrict__ Wd,
                                              const float* __restrict__ Bd) {
    int linear = blockIdx.x * 256 + threadIdx.x;
    int c = linear & 127;
    int pq = linear >> 7;
    int img = pq / 6400;
    int q = pq - img * 6400;
    int h = q / 40;
    int w4 = (q - h * 40) * 4;
    float wt[9];
#pragma unroll
    for (int t = 0; t < 9; t++) wt[t] = __ldg(&Wd[t * 128 + c]);
    float a[4];
    float bv = __ldg(&Bd[c]);
#pragma unroll
    for (int j = 0; j < 4; j++) a[j] = bv;
    const float* basep = g_h + (size_t)img * HW * 128 + c;
#pragma unroll
    for (int dy = 0; dy < 3; dy++) {
        int y = h + dy - 1;
        if ((unsigned)y >= 160u) continue;
        const float* row = basep + (size_t)y * 160 * 128;
#pragma unroll
        for (int t = 0; t < 6; t++) {
            int x = w4 + t - 1;
            if ((unsigned)x >= 160u) continue;
            float v = __ldg(&row[(size_t)x * 128]);
#pragma unroll
            for (int j = 0; j < 4; j++) {
                int dx = t - j;
                if (dx >= 0 && dx <= 2) a[j] += v * wt[dy * 3 + dx];
            }
        }
    }
    size_t o = ((size_t)pq * 4) * 128 + c;
#pragma unroll
    for (int j = 0; j < 4; j++) g_dw[o + (size_t)j * 128] = a[j];
}

// ------------------------- fused: deformable sample + outp GEMM (bf16) + SimpleGate -------------------------
__device__ __forceinline__ void fma4(float4& a, float w, const float4 v) {
    a.x += w * v.x; a.y += w * v.y; a.z += w * v.z; a.w += w * v.w;
}

__global__ void __launch_bounds__(256) k_souter(const float* __restrict__ Wo,
                                                const float* __restrict__ Bo) {
    extern __shared__ uint32_t smu[];
    uint32_t* Wb = smu;                         // 128*68 words
    uint32_t* Xb = smu + 128 * 68;              // 64*68 words (sampled, bf16)
    float* OMs = (float*)(Xb + 64 * 68);        // 8 warps * 112
    int tid = threadIdx.x;
    int base = blockIdx.x * 64;
    int img = base / HW;
    int pbase = base - img * HW;
    for (int i = tid; i < 4096; i += 256) {
        int row = i >> 5, q = i & 31;
        float4 v = *(const float4*)&Wo[row * 128 + q * 4];
        Wb[row * 68 + q * 2] = pk(v.x, v.y);
        Wb[row * 68 + q * 2 + 1] = pk(v.z, v.w);
    }
    int wrp = tid >> 5, lane = tid & 31;
    int g = lane >> 3, c4 = lane & 7;
    const float* vg = g_v + (size_t)img * HW * 128 + g * 32 + c4 * 4;
    float* oms = OMs + wrp * 112;
    for (int p8 = 0; p8 < 8; p8++) {
        int px = wrp * 8 + p8;
        int pos = pbase + px;
        int hh = pos / 160, ww = pos - hh * 160;
        const float* omp = g_om + ((size_t)img * HW + pos) * 112;
        __syncwarp();
        oms[lane] = omp[lane];
        oms[32 + lane] = omp[32 + lane];
        oms[64 + lane] = omp[64 + lane];
        if (lane < 12) oms[96 + lane] = omp[96 + lane];
        __syncwarp();
        float4 acc = make_float4(0.f, 0.f, 0.f, 0.f);
#pragma unroll
        for (int k = 0; k < 9; k++) {
            float ox = oms[g * 27 + k * 3 + 0];
            float oy = oms[g * 27 + k * 3 + 1];
            float mk = oms[g * 27 + k * 3 + 2];
            float fx = (float)(ww + (k % 3) - 1) + ox;
            float fy = (float)(hh + (k / 3) - 1) + oy;
            float x0f = floorf(fx), y0f = floorf(fy);
            float tx = fx - x0f, ty = fy - y0f;
            int ix = (int)x0f, iy = (int)y0f;
            float w00 = (1.f - tx) * (1.f - ty) * mk;
            float w01 = tx * (1.f - ty) * mk;
            float w10 = (1.f - tx) * ty * mk;
            float w11 = tx * ty * mk;
            if ((unsigned)iy < 160u) {
                if ((unsigned)ix < 160u)
                    fma4(acc, w00, *(const float4*)&vg[(size_t)(iy * 160 + ix) * 128]);
                if ((unsigned)(ix + 1) < 160u)
                    fma4(acc, w01, *(const float4*)&vg[(size_t)(iy * 160 + ix + 1) * 128]);
            }
            if ((unsigned)(iy + 1) < 160u) {
                if ((unsigned)ix < 160u)
                    fma4(acc, w10, *(const float4*)&vg[(size_t)((iy + 1) * 160 + ix) * 128]);
                if ((unsigned)(ix + 1) < 160u)
                    fma4(acc, w11, *(const float4*)&vg[(size_t)((iy + 1) * 160 + ix + 1) * 128]);
            }
        }
        Xb[px * 68 + lane * 2] = pk(acc.x, acc.y);
        Xb[px * 68 + lane * 2 + 1] = pk(acc.z, acc.w);
    }
    __syncthreads();
    // GEMM + gate: 8 warps, wm in {0,1} (rows), wn in {0..3}; nt pairs gate halves
    int wm = wrp & 1, wn = wrp >> 1;
    int gid = lane >> 2, tig = lane & 3;
    float c[2][4][4];
#pragma unroll
    for (int nt = 0; nt < 4; nt++) {
        int o = wn * 16 + (nt & 1) * 8 + (nt >> 1) * 64 + 2 * tig;
        float b0 = Bo[o], b1 = Bo[o + 1];
#pragma unroll
        for (int mt = 0; mt < 2; mt++) {
            c[mt][nt][0] = b0; c[mt][nt][1] = b1;
            c[mt][nt][2] = b0; c[mt][nt][3] = b1;
        }
    }
#pragma unroll
    for (int kw = 0; kw < 64; kw += 8) {
        uint32_t A[2][4];
#pragma unroll
        for (int mt = 0; mt < 2; mt++) {
            int r = wm * 32 + mt * 16 + gid;
            A[mt][0] = Xb[r * 68 + kw + tig];
            A[mt][1] = Xb[(r + 8) * 68 + kw + tig];
            A[mt][2] = Xb[r * 68 + kw + 4 + tig];
            A[mt][3] = Xb[(r + 8) * 68 + kw + 4 + tig];
        }
#pragma unroll
        for (int nt = 0; nt < 4; nt++) {
            int n = wn * 16 + (nt & 1) * 8 + (nt >> 1) * 64 + gid;
            uint32_t Bf[2];
            Bf[0] = Wb[n * 68 + kw + tig];
            Bf[1] = Wb[n * 68 + kw + 4 + tig];
#pragma unroll
            for (int mt = 0; mt < 2; mt++) mma_bf16(c[mt][nt], A[mt], Bf);
        }
    }
#pragma unroll
    for (int mt = 0; mt < 2; mt++) {
        size_t r0 = base + wm * 32 + mt * 16 + gid;
#pragma unroll
        for (int ntp = 0; ntp < 2; ntp++) {
            int o = wn * 16 + ntp * 8 + 2 * tig;
            *(float2*)&g_f[r0 * 64 + o] =
                make_float2(c[mt][ntp][0] * c[mt][ntp + 2][0], c[mt][ntp][1] * c[mt][ntp + 2][1]);
            *(float2*)&g_f[(r0 + 8) * 64 + o] =
                make_float2(c[mt][ntp][2] * c[mt][ntp + 2][2], c[mt][ntp][3] * c[mt][ntp + 2][3]);
        }
    }
}

// ------------------------- pooling partials -------------------------
__global__ void __launch_bounds__(256) k_pool() {
    __shared__ float sh[256];
    int img = blockIdx.x >> 4, seg = blockIdx.x & 15;
    int tid = threadIdx.x;
    int c = tid & 63, q = tid >> 6;
    const float* fp = g_f + ((size_t)img * HW + seg * 1600) * 64;
    float s = 0.f;
    for (int n = 0; n < 400; n++) s += fp[(size_t)(q + 4 * n) * 64 + c];
    sh[tid] = s;
    __syncthreads();
    if (tid < 64)
        g_part[(img * 16 + seg) * 64 + tid] = sh[tid] + sh[tid + 64] + sh[tid + 128] + sh[tid + 192];
}

// ------------------------- finish pooling + SCA projection -------------------------
__global__ void __launch_bounds__(256) k_sca(const float* __restrict__ sw, const float* __restrict__ sb) {
    __shared__ float shp[256];
    int tid = threadIdx.x;
    int b = tid >> 7, c = tid & 127;
    int img = (c < 64) ? b : (2 + b);
    int cc = c & 63;
    float s = 0.f;
    for (int seg = 0; seg < 16; seg++) s += g_part[(img * 16 + seg) * 64 + cc];
    shp[tid] = s * (1.f / (float)HW);
    __syncthreads();
    float acc = __ldg(&sb[c]);
    for (int k = 0; k < 128; k++) acc += shp[b * 128 + k] * __ldg(&sw[c * 128 + k]);
    g_s[tid] = acc;
}

// ------------------------- SCA-folded conv3 + dual residual -> g_y -------------------------
__global__ void __launch_bounds__(256) k_conv3_y(const float* __restrict__ W3,
                                                 const float* __restrict__ B3,
                                                 const float* __restrict__ beta,
                                                 const float* __restrict__ x_l,
                                                 const float* __restrict__ x_r) {
    extern __shared__ float sm[];
    float* Fs = sm;              // 64*132
    float* W3s = sm + 64 * 132;  // 64*128 (scale-folded)
    int tid = threadIdx.x;
    int base = blockIdx.x * 64;
    int b = base / HW;
    int pos = base - b * HW;
    for (int i = tid; i < 64 * 128; i += 256) {
        int p = i >> 7, o = i & 127;
        float v = (o < 64) ? g_f[((size_t)b * HW + pos + p) * 64 + o]
                           : g_f[((size_t)(2 + b) * HW + pos + p) * 64 + (o - 64)];
        Fs[p * 132 + o] = v;
    }
    for (int i = tid; i < 64 * 128; i += 256) {
        int o = i & 127;
        W3s[i] = W3[i] * g_s[b * 128 + o];
    }
    __syncthreads();
    int pr = tid & 15, og = tid >> 4;
    float acc[4][4];
#pragma unroll
    for (int j = 0; j < 4; j++) {
        float bv = B3[og * 4 + j];
#pragma unroll
        for (int i = 0; i < 4; i++) acc[i][j] = bv;
    }
#pragma unroll 4
    for (int k = 0; k < 128; k += 4) {
        float4 xv[4];
#pragma unroll
        for (int i = 0; i < 4; i++) xv[i] = *(const float4*)&Fs[(pr + 16 * i) * 132 + k];
#pragma unroll
        for (int j = 0; j < 4; j++) {
            float4 wv = *(const float4*)&W3s[(og * 4 + j) * 128 + k];
#pragma unroll
            for (int i = 0; i < 4; i++)
                acc[i][j] += xv[i].x * wv.x + xv[i].y * wv.y + xv[i].z * wv.z + xv[i].w * wv.w;
        }
    }
#pragma unroll
    for (int i = 0; i < 4; i++) {
        int p = pr + 16 * i;
#pragma unroll
        for (int j = 0; j < 4; j++) {
            int jj = og * 4 + j;
            float bt = __ldg(&beta[jj]);
            float x3 = acc[i][j] * bt;
            float xl = x_l[((size_t)b * 64 + jj) * HW + pos + p];
            float xr = x_r[((size_t)b * 64 + jj) * HW + pos + p];
            g_y[(size_t)(base + p) * 128 + jj] = xl + x3;
            g_y[(size_t)(base + p) * 128 + 64 + jj] = xr + x3;
        }
    }
}

// ------------------------- LN2(128ch) + conv4 (bf16 mma) + gate -> g_zg -------------------------
__global__ void __launch_bounds__(256) k_ln2c4(const float* __restrict__ g2,
                                               const float* __restrict__ W4,
                                               const float* __restrict__ B4) {
    extern __shared__ float sm[];
    float* Yf = sm;                                 // 64*132 fp32
    uint32_t* Yb = (uint32_t*)(sm + 64 * 132);      // 64*68 words
    uint32_t* Wb = Yb + 64 * 68;                    // 128*68 words
    float* mr = (float*)(Wb + 128 * 68);            // 128
    int tid = threadIdx.x;
    int base = blockIdx.x * 64;
    for (int i = tid; i < 64 * 128; i += 256) {
        int p = i >> 7, c = i & 127;
        Yf[p * 132 + c] = g_y[(size_t)(base + p) * 128 + c];
    }
    for (int i = tid; i < 4096; i += 256) {
        int row = i >> 5, q = i & 31;
        float4 v = *(const float4*)&W4[row * 128 + q * 4];
        Wb[row * 68 + q * 2] = pk(v.x, v.y);
        Wb[row * 68 + q * 2 + 1] = pk(v.z, v.w);
    }
    __syncthreads();
    if (tid < 64) {
        float s = 0.f, sq = 0.f;
        for (int c = 0; c < 128; c++) { float v = Yf[tid * 132 + c]; s += v; sq += v * v; }
        float m = s * (1.f / 128.f);
        float var = sq * (1.f / 128.f) - m * m;
        mr[tid] = m; mr[64 + tid] = rsqrtf(var + 1e-5f);
    }
    __syncthreads();
    for (int i = tid; i < 64 * 64; i += 256) {
        int p = i >> 6, q = i & 63;
        int k0 = q * 2;
        float f0 = (Yf[p * 132 + k0] - mr[p]) * mr[64 + p] * __ldg(&g2[k0]);
        float f1 = (Yf[p * 132 + k0 + 1] - mr[p]) * mr[64 + p] * __ldg(&g2[k0 + 1]);
        Yb[p * 68 + q] = pk(f0, f1);
    }
    __syncthreads();
    int wid = tid >> 5, lane = tid & 31;
    int wm = wid & 1, wn = wid >> 1;
    int gid = lane >> 2, tig = lane & 3;
    float c[2][4][4];
#pragma unroll
    for (int nt = 0; nt < 4; nt++) {
        int o = wn * 16 + (nt & 1) * 8 + (nt >> 1) * 64 + 2 * tig;
        float b0 = B4[o], b1 = B4[o + 1];
#pragma unroll
        for (int mt = 0; mt < 2; mt++) {
            c[mt][nt][0] = b0; c[mt][nt][1] = b1;
            c[mt][nt][2] = b0; c[mt][nt][3] = b1;
        }
    }
#pragma unroll
    for (int kw = 0; kw < 64; kw += 8) {
        uint32_t A[2][4];
#pragma unroll
        for (int mt = 0; mt < 2; mt++) {
            int r = wm * 32 + mt * 16 + gid;
            A[mt][0] = Yb[r * 68 + kw + tig];
            A[mt][1] = Yb[(r + 8) * 68 + kw + tig];
            A[mt][2] = Yb[r * 68 + kw + 4 + tig];
            A[mt][3] = Yb[(r + 8) * 68 + kw + 4 + tig];
        }
#pragma unroll
        for (int nt = 0; nt < 4; nt++) {
            int n = wn * 16 + (nt & 1) * 8 + (nt >> 1) * 64 + gid;
            uint32_t Bf[2];
            Bf[0] = Wb[n * 68 + kw + tig];
            Bf[1] = Wb[n * 68 + kw + 4 + tig];
#pragma unroll
            for (int mt = 0; mt < 2; mt++) mma_bf16(c[mt][nt], A[mt], Bf);
        }
    }
#pragma unroll
    for (int mt = 0; mt < 2; mt++) {
        size_t r0 = base + wm * 32 + mt * 16 + gid;
#pragma unroll
        for (int ntp = 0; ntp < 2; ntp++) {
            int o = wn * 16 + ntp * 8 + 2 * tig;
            *(float2*)&g_zg[r0 * 64 + o] =
                make_float2(c[mt][ntp][0] * c[mt][ntp + 2][0], c[mt][ntp][1] * c[mt][ntp + 2][1]);
            *(float2*)&g_zg[(r0 + 8) * 64 + o] =
                make_float2(c[mt][ntp][2] * c[mt][ntp + 2][2], c[mt][ntp][3] * c[mt][ntp + 2][3]);
        }
    }
}

// ------------------------- conv5 + final residuals, NCHW outputs -------------------------
__global__ void __launch_bounds__(256) k_c5out(const float* __restrict__ W5,
                                               const float* __restrict__ B5,
                                               const float* __restrict__ gamma,
                                               float* __restrict__ out) {
    extern __shared__ float sm[];
    float* Zs = sm;                    // 64*68
    float* W5s = sm + 64 * 68;         // 64*64
    float* Ys = W5s + 64 * 64;         // 64*132
    int tid = threadIdx.x;
    int base = blockIdx.x * 64;
    int b = base / HW;
    int pos = base - b * HW;
    for (int i = tid; i < 64 * 64; i += 256) {
        int p = i >> 6, k = i & 63;
        Zs[p * 68 + k] = g_zg[(size_t)(base + p) * 64 + k];
    }
    for (int i = tid; i < 64 * 64; i += 256) W5s[i] = W5[i];
    for (int i = tid; i < 64 * 128; i += 256) {
        int p = i >> 7, c = i & 127;
        Ys[p * 132 + c] = g_y[(size_t)(base + p) * 128 + c];
    }
    __syncthreads();
    int pr = tid & 15, og = tid >> 4;
    float acc[4][4];
#pragma unroll
    for (int j = 0; j < 4; j++) {
        float bv = B5[og * 4 + j];
#pragma unroll
        for (int i = 0; i < 4; i++) acc[i][j] = bv;
    }
#pragma unroll 4
    for (int k = 0; k < 64; k += 4) {
        float4 xv[4];
#pragma unroll
        for (int i = 0; i < 4; i++) xv[i] = *(const float4*)&Zs[(pr + 16 * i) * 68 + k];
#pragma unroll
        for (int j = 0; j < 4; j++) {
            float4 wv = *(const float4*)&W5s[(og * 4 + j) * 64 + k];
#pragma unroll
            for (int i = 0; i < 4; i++)
                acc[i][j] += xv[i].x * wv.x + xv[i].y * wv.y + xv[i].z * wv.z + xv[i].w * wv.w;
        }
    }
    const size_t HALF = (size_t)2 * 64 * HW;
#pragma unroll
    for (int i = 0; i < 4; i++) {
        int p = pr + 16 * i;
#pragma unroll
        for (int j = 0; j < 4; j++) {
            int cc = og * 4 + j;
            float z = acc[i][j] * __ldg(&gamma[cc]);
            size_t o = ((size_t)b * 64 + cc) * HW + pos + p;
            out[o] = Ys[p * 132 + cc] + z;
            out[HALF + o] = Ys[p * 132 + 64 + cc] + z;
        }
    }
}

// ------------------------- host -------------------------
extern "C" void kernel_launch(void* const* d_in, const int* in_sizes, int n_in,
                              void* d_out, int out_size) {
    const float* x_l     = (const float*)d_in[0];
    const float* x_r     = (const float*)d_in[1];
    const float* ln1_g   = (const float*)d_in[2];
    const float* pw1_w   = (const float*)d_in[3];
    const float* pw1_b   = (const float*)d_in[4];
    const float* val_w   = (const float*)d_in[5];
    const float* val_b   = (const float*)d_in[6];
    const float* dwc_w   = (const float*)d_in[7];
    const float* dwc_b   = (const float*)d_in[8];
    const float* om_w    = (const float*)d_in[9];
    const float* om_b    = (const float*)d_in[10];
    const float* outp_w  = (const float*)d_in[11];
    const float* outp_b  = (const float*)d_in[12];
    const float* sca_w   = (const float*)d_in[13];
    const float* sca_b   = (const float*)d_in[14];
    const float* conv3_w = (const float*)d_in[15];
    const float* conv3_b = (const float*)d_in[16];
    const float* norm2_g = (const float*)d_in[17];
    const float* conv4_w = (const float*)d_in[18];
    const float* conv4_b = (const float*)d_in[19];
    const float* conv5_w = (const float*)d_in[20];
    const float* conv5_b = (const float*)d_in[21];
    const float* beta    = (const float*)d_in[22];
    const float* gamma   = (const float*)d_in[23];
    float* out = (float*)d_out;

    float *ph, *pv, *pdw, *pom;
    cudaGetSymbolAddress((void**)&ph, g_h);
    cudaGetSymbolAddress((void**)&pv, g_v);
    cudaGetSymbolAddress((void**)&pdw, g_dw);
    cudaGetSymbolAddress((void**)&pom, g_om);

    const int SM_LNPW1 = (64 * 68 + 64 * 36 + 128 * 36 + 128) * 4;       // ~45.6 KB
    const int SM_TG    = (2 * 128 * 68) * 4;                             // 69632
    const int SM_SOUT  = (128 * 68 + 64 * 68 + 8 * 112) * 4;             // 55808
    const int SM_C3    = (64 * 132 + 64 * 128) * 4;
    const int SM_LN2   = (64 * 132 + 64 * 68 + 128 * 68 + 128) * 4;      // 86528
    const int SM_C5    = (64 * 68 + 64 * 64 + 64 * 132) * 4;

    cudaFuncSetAttribute(k_ln_pw1,  cudaFuncAttributeMaxDynamicSharedMemorySize, SM_LNPW1);
    cudaFuncSetAttribute(k_tg<128>, cudaFuncAttributeMaxDynamicSharedMemorySize, SM_TG);
    cudaFuncSetAttribute(k_tg<112>, cudaFuncAttributeMaxDynamicSharedMemorySize, SM_TG);
    cudaFuncSetAttribute(k_souter,  cudaFuncAttributeMaxDynamicSharedMemorySize, SM_SOUT);
    cudaFuncSetAttribute(k_conv3_y, cudaFuncAttributeMaxDynamicSharedMemorySize, SM_C3);
    cudaFuncSetAttribute(k_ln2c4,   cudaFuncAttributeMaxDynamicSharedMemorySize, SM_LN2);
    cudaFuncSetAttribute(k_c5out,   cudaFuncAttributeMaxDynamicSharedMemorySize, SM_C5);

    k_ln_pw1  <<<P4 / 64, 256, SM_LNPW1>>>(x_l, x_r, ln1_g, pw1_w, pw1_b);
    k_tg<128> <<<P4 / 128, 256, SM_TG>>>(ph, pv, val_w, val_b);       // value proj
    k_dwc4    <<<P4 * 128 / (256 * 4), 256>>>(dwc_w, dwc_b);
    k_tg<112> <<<P4 / 128, 256, SM_TG>>>(pdw, pom, om_w, om_b);       // offset/mask proj
    k_souter  <<<P4 / 64, 256, SM_SOUT>>>(outp_w, outp_b);
    k_pool    <<<64, 256>>>();
    k_sca     <<<1, 256>>>(sca_w, sca_b);
    k_conv3_y <<<P2 / 64, 256, SM_C3>>>(conv3_w, conv3_b, beta, x_l, x_r);
    k_ln2c4   <<<P2 / 64, 256, SM_LN2>>>(norm2_g, conv4_w, conv4_b);
    k_c5out   <<<P2 / 64, 256, SM_C5>>>(conv5_w, conv5_b, gamma, out);
}

// round 6
// speedup vs baseline: 2.3656x; 1.0609x over previous
#include <cuda_runtime.h>
#include <cuda_bf16.h>
#include <cstdint>

#define HW 25600
#define P4 102400   // 4 images * HW  (img 0,1 = x_l b0,b1 ; img 2,3 = x_r b0,b1)
#define P2 51200    // 2 batches * HW

// ------------------------- scratch (__device__ globals) -------------------------
__device__ __nv_bfloat16 g_h[(size_t)P4 * 128];   // LN1+pw1 out, NHWC (bf16)
__device__ __nv_bfloat16 g_v[(size_t)P4 * 128];   // value proj (bf16)
__device__ __nv_bfloat16 g_dw[(size_t)P4 * 128];  // depthwise conv out (bf16)
__device__ float g_om[(size_t)P4 * 112];          // offset/mask proj (fp32)
__device__ float g_f[(size_t)P4 * 64];            // gated branch features
__device__ float g_y[(size_t)P2 * 128];           // [y_l(64) ; y_r(64)] NHWC per batch
__device__ float g_zg[(size_t)P2 * 64];           // gated conv4 output
__device__ float g_part[64 * 64];                 // pooling partials
__device__ float g_s[256];                        // SCA scale s[b][128]

// ------------------------- bf16 helpers -------------------------
__device__ __forceinline__ uint32_t pk(float a, float b) {
    __nv_bfloat162 t = __floats2bfloat162_rn(a, b);
    return *reinterpret_cast<uint32_t*>(&t);
}
__device__ __forceinline__ float4 ld4bf(const __nv_bfloat16* p) {
    uint2 u = *(const uint2*)p;
    __nv_bfloat162 a = *reinterpret_cast<__nv_bfloat162*>(&u.x);
    __nv_bfloat162 b = *reinterpret_cast<__nv_bfloat162*>(&u.y);
    float2 fa = __bfloat1622float2(a), fb = __bfloat1622float2(b);
    return make_float4(fa.x, fa.y, fb.x, fb.y);
}
__device__ __forceinline__ void mma_bf16(float* c, const uint32_t* a, const uint32_t* b) {
    asm volatile(
        "mma.sync.aligned.m16n8k16.row.col.f32.bf16.bf16.f32 "
        "{%0,%1,%2,%3}, {%4,%5,%6,%7}, {%8,%9}, {%0,%1,%2,%3};"
        : "+f"(c[0]), "+f"(c[1]), "+f"(c[2]), "+f"(c[3])
        : "r"(a[0]), "r"(a[1]), "r"(a[2]), "r"(a[3]), "r"(b[0]), "r"(b[1]));
}

// ------------------------- kernel 1: LN(64ch) + pw1 (64 -> 128), bf16 mma -------------------------
__global__ void __launch_bounds__(256) k_ln_pw1(const float* __restrict__ x_l,
                                                const float* __restrict__ x_r,
                                                const float* __restrict__ g1,
                                                const float* __restrict__ W,
                                                const float* __restrict__ Bb) {
    extern __shared__ float sm[];
    float* Xf = sm;                            // 64*68 fp32
    uint32_t* Xb = (uint32_t*)(sm + 64 * 68);  // 64*36 words (bf16 pairs, K=64)
    uint32_t* Wb = Xb + 64 * 36;               // 128*36 words
    float* mr = (float*)(Wb + 128 * 36);       // 128
    int tid = threadIdx.x;
    int base = blockIdx.x * 64;
    int img = base / HW;
    int pos = base - img * HW;
    const float* xp = (img < 2) ? (x_l + (size_t)img * HW * 64)
                                : (x_r + (size_t)(img - 2) * HW * 64);
    for (int i = tid; i < 64 * 64; i += 256) {
        int c = i >> 6, p = i & 63;
        Xf[p * 68 + c] = xp[(size_t)c * HW + pos + p];
    }
    for (int i = tid; i < 128 * 16; i += 256) {
        int row = i >> 4, q = i & 15;
        float4 v = *(const float4*)&W[row * 64 + q * 4];
        Wb[row * 36 + q * 2] = pk(v.x, v.y);
        Wb[row * 36 + q * 2 + 1] = pk(v.z, v.w);
    }
    __syncthreads();
    if (tid < 64) {
        float s = 0.f, sq = 0.f;
        for (int c = 0; c < 64; c++) { float v = Xf[tid * 68 + c]; s += v; sq += v * v; }
        float m = s * (1.f / 64.f);
        float var = sq * (1.f / 64.f) - m * m;
        mr[tid] = m; mr[64 + tid] = rsqrtf(var + 1e-5f);
    }
    __syncthreads();
    for (int i = tid; i < 64 * 32; i += 256) {
        int p = i >> 5, q = i & 31;
        int k0 = q * 2;
        float f0 = (Xf[p * 68 + k0] - mr[p]) * mr[64 + p] * __ldg(&g1[k0]);
        float f1 = (Xf[p * 68 + k0 + 1] - mr[p]) * mr[64 + p] * __ldg(&g1[k0 + 1]);
        Xb[p * 36 + q] = pk(f0, f1);
    }
    __syncthreads();
    int wid = tid >> 5, lane = tid & 31;
    int wm = wid & 1, wn = wid >> 1;
    int gid = lane >> 2, tig = lane & 3;
    float c[2][4][4];
#pragma unroll
    for (int nt = 0; nt < 4; nt++) {
        int o = wn * 32 + nt * 8 + 2 * tig;
        float b0 = Bb[o], b1 = Bb[o + 1];
#pragma unroll
        for (int mt = 0; mt < 2; mt++) {
            c[mt][nt][0] = b0; c[mt][nt][1] = b1;
            c[mt][nt][2] = b0; c[mt][nt][3] = b1;
        }
    }
#pragma unroll
    for (int kw = 0; kw < 32; kw += 8) {
        uint32_t A[2][4];
#pragma unroll
        for (int mt = 0; mt < 2; mt++) {
            int r = wm * 32 + mt * 16 + gid;
            A[mt][0] = Xb[r * 36 + kw + tig];
            A[mt][1] = Xb[(r + 8) * 36 + kw + tig];
            A[mt][2] = Xb[r * 36 + kw + 4 + tig];
            A[mt][3] = Xb[(r + 8) * 36 + kw + 4 + tig];
        }
#pragma unroll
        for (int nt = 0; nt < 4; nt++) {
            int n = wn * 32 + nt * 8 + gid;
            uint32_t Bf[2];
            Bf[0] = Wb[n * 36 + kw + tig];
            Bf[1] = Wb[n * 36 + kw + 4 + tig];
#pragma unroll
            for (int mt = 0; mt < 2; mt++) mma_bf16(c[mt][nt], A[mt], Bf);
        }
    }
    uint32_t* gh = (uint32_t*)g_h;
#pragma unroll
    for (int mt = 0; mt < 2; mt++) {
        size_t r0 = base + wm * 32 + mt * 16 + gid;
#pragma unroll
        for (int nt = 0; nt < 4; nt++) {
            int o = wn * 32 + nt * 8 + 2 * tig;
            gh[r0 * 64 + o / 2] = pk(c[mt][nt][0], c[mt][nt][1]);
            gh[(r0 + 8) * 64 + o / 2] = pk(c[mt][nt][2], c[mt][nt][3]);
        }
    }
}

// ------------------------- bf16 tensor GEMM: 128px x N, K=128, bf16 input -------------------------
template <int N, bool OBF>
__global__ void __launch_bounds__(256) k_tg(const __nv_bfloat16* __restrict__ X,
                                            void* __restrict__ Y,
                                            const float* __restrict__ W,
                                            const float* __restrict__ Bb) {
    extern __shared__ uint32_t smu[];
    uint32_t* Xu = smu;              // 128*68 words
    uint32_t* Wu = smu + 128 * 68;   // 128*68 words (rows >= N zeroed)
    int tid = threadIdx.x;
    size_t base = (size_t)blockIdx.x * 128;
    const uint2* Xg = (const uint2*)X;     // 4 bf16 per uint2
    for (int i = tid; i < 4096; i += 256) {
        int row = i >> 5, q = i & 31;
        uint2 u = __ldg(&Xg[(base + row) * 32 + q]);
        Xu[row * 68 + q * 2] = u.x;
        Xu[row * 68 + q * 2 + 1] = u.y;
    }
    for (int i = tid; i < 4096; i += 256) {
        int row = i >> 5, q = i & 31;
        uint32_t lo = 0u, hi = 0u;
        if (row < N) {
            float4 v = *(const float4*)&W[row * 128 + q * 4];
            lo = pk(v.x, v.y); hi = pk(v.z, v.w);
        }
        Wu[row * 68 + q * 2] = lo;
        Wu[row * 68 + q * 2 + 1] = hi;
    }
    __syncthreads();
    int wid = tid >> 5, lane = tid & 31;
    int wm = wid & 3, wn = wid >> 2;
    int gid = lane >> 2, tig = lane & 3;
    float c[2][8][4];
#pragma unroll
    for (int nt = 0; nt < 8; nt++) {
        int o = wn * 64 + nt * 8 + 2 * tig;
        float b0 = (o < N) ? Bb[o] : 0.f;
        float b1 = (o + 1 < N) ? Bb[o + 1] : 0.f;
#pragma unroll
        for (int mt = 0; mt < 2; mt++) {
            c[mt][nt][0] = b0; c[mt][nt][1] = b1;
            c[mt][nt][2] = b0; c[mt][nt][3] = b1;
        }
    }
#pragma unroll
    for (int kw = 0; kw < 64; kw += 8) {
        uint32_t A[2][4];
#pragma unroll
        for (int mt = 0; mt < 2; mt++) {
            int r = wm * 32 + mt * 16 + gid;
            A[mt][0] = Xu[r * 68 + kw + tig];
            A[mt][1] = Xu[(r + 8) * 68 + kw + tig];
            A[mt][2] = Xu[r * 68 + kw + 4 + tig];
            A[mt][3] = Xu[(r + 8) * 68 + kw + 4 + tig];
        }
        uint32_t Bf[8][2];
#pragma unroll
        for (int nt = 0; nt < 8; nt++) {
            int n = wn * 64 + nt * 8 + gid;
            Bf[nt][0] = Wu[n * 68 + kw + tig];
            Bf[nt][1] = Wu[n * 68 + kw + 4 + tig];
        }
#pragma unroll
        for (int mt = 0; mt < 2; mt++)
#pragma unroll
            for (int nt = 0; nt < 8; nt++)
                mma_bf16(c[mt][nt], A[mt], Bf[nt]);
    }
#pragma unroll
    for (int mt = 0; mt < 2; mt++) {
        size_t r0 = base + wm * 32 + mt * 16 + gid;
#pragma unroll
        for (int nt = 0; nt < 8; nt++) {
            int o = wn * 64 + nt * 8 + 2 * tig;
            if (o < N) {
                if (OBF) {
                    uint32_t* Yu = (uint32_t*)Y;
                    Yu[r0 * (N / 2) + o / 2] = pk(c[mt][nt][0], c[mt][nt][1]);
                    Yu[(r0 + 8) * (N / 2) + o / 2] = pk(c[mt][nt][2], c[mt][nt][3]);
                } else {
                    float* Yf = (float*)Y;
                    *(float2*)&Yf[r0 * N + o] = make_float2(c[mt][nt][0], c[mt][nt][1]);
                    *(float2*)&Yf[(r0 + 8) * N + o] = make_float2(c[mt][nt][2], c[mt][nt][3]);
                }
            }
        }
    }
}

// ------------------------- depthwise 3x3, 4 px per thread (bf16 in/out) -------------------------
__global__ void __launch_bounds__(256) k_dwc4(const float* __restrict__ Wd,
                                              const float* __restrict__ Bd) {
    int linear = blockIdx.x * 256 + threadIdx.x;
    int c = linear & 127;
    int pq = linear >> 7;
    int img = pq / 6400;
    int q = pq - img * 6400;
    int h = q / 40;
    int w4 = (q - h * 40) * 4;
    float wt[9];
#pragma unroll
    for (int t = 0; t < 9; t++) wt[t] = __ldg(&Wd[t * 128 + c]);
    float a[4];
    float bv = __ldg(&Bd[c]);
#pragma unroll
    for (int j = 0; j < 4; j++) a[j] = bv;
    const __nv_bfloat16* basep = g_h + (size_t)img * HW * 128 + c;
#pragma unroll
    for (int dy = 0; dy < 3; dy++) {
        int y = h + dy - 1;
        if ((unsigned)y >= 160u) continue;
        const __nv_bfloat16* row = basep + (size_t)y * 160 * 128;
#pragma unroll
        for (int t = 0; t < 6; t++) {
            int x = w4 + t - 1;
            if ((unsigned)x >= 160u) continue;
            float v = __bfloat162float(row[(size_t)x * 128]);
#pragma unroll
            for (int j = 0; j < 4; j++) {
                int dx = t - j;
                if (dx >= 0 && dx <= 2) a[j] += v * wt[dy * 3 + dx];
            }
        }
    }
    size_t o = ((size_t)pq * 4) * 128 + c;
#pragma unroll
    for (int j = 0; j < 4; j++) g_dw[o + (size_t)j * 128] = __float2bfloat16_rn(a[j]);
}

// ------------------------- fused: deformable sample + outp GEMM (bf16) + SimpleGate -------------------------
__device__ __forceinline__ void fma4(float4& a, float w, const float4 v) {
    a.x += w * v.x; a.y += w * v.y; a.z += w * v.z; a.w += w * v.w;
}

__global__ void __launch_bounds__(256) k_souter(const float* __restrict__ Wo,
                                                const float* __restrict__ Bo) {
    extern __shared__ uint32_t smu[];
    uint32_t* Wb = smu;                         // 128*68 words
    uint32_t* Xb = smu + 128 * 68;              // 64*68 words (sampled, bf16)
    float* OMs = (float*)(Xb + 64 * 68);        // 8 warps * 112
    int tid = threadIdx.x;
    int base = blockIdx.x * 64;
    int img = base / HW;
    int pbase = base - img * HW;
    for (int i = tid; i < 4096; i += 256) {
        int row = i >> 5, q = i & 31;
        float4 v = *(const float4*)&Wo[row * 128 + q * 4];
        Wb[row * 68 + q * 2] = pk(v.x, v.y);
        Wb[row * 68 + q * 2 + 1] = pk(v.z, v.w);
    }
    int wrp = tid >> 5, lane = tid & 31;
    int g = lane >> 3, c4 = lane & 7;
    const __nv_bfloat16* vg = g_v + (size_t)img * HW * 128 + g * 32 + c4 * 4;
    float* oms = OMs + wrp * 112;
    for (int p8 = 0; p8 < 8; p8++) {
        int px = wrp * 8 + p8;
        int pos = pbase + px;
        int hh = pos / 160, ww = pos - hh * 160;
        const float* omp = g_om + ((size_t)img * HW + pos) * 112;
        __syncwarp();
        oms[lane] = omp[lane];
        oms[32 + lane] = omp[32 + lane];
        oms[64 + lane] = omp[64 + lane];
        if (lane < 12) oms[96 + lane] = omp[96 + lane];
        __syncwarp();
        float4 acc = make_float4(0.f, 0.f, 0.f, 0.f);
#pragma unroll
        for (int k = 0; k < 9; k++) {
            float ox = oms[g * 27 + k * 3 + 0];
            float oy = oms[g * 27 + k * 3 + 1];
            float mk = oms[g * 27 + k * 3 + 2];
            float fx = (float)(ww + (k % 3) - 1) + ox;
            float fy = (float)(hh + (k / 3) - 1) + oy;
            float x0f = floorf(fx), y0f = floorf(fy);
            float tx = fx - x0f, ty = fy - y0f;
            int ix = (int)x0f, iy = (int)y0f;
            float w00 = (1.f - tx) * (1.f - ty) * mk;
            float w01 = tx * (1.f - ty) * mk;
            float w10 = (1.f - tx) * ty * mk;
            float w11 = tx * ty * mk;
            if ((unsigned)iy < 160u) {
                if ((unsigned)ix < 160u)
                    fma4(acc, w00, ld4bf(&vg[(size_t)(iy * 160 + ix) * 128]));
                if ((unsigned)(ix + 1) < 160u)
                    fma4(acc, w01, ld4bf(&vg[(size_t)(iy * 160 + ix + 1) * 128]));
            }
            if ((unsigned)(iy + 1) < 160u) {
                if ((unsigned)ix < 160u)
                    fma4(acc, w10, ld4bf(&vg[(size_t)((iy + 1) * 160 + ix) * 128]));
                if ((unsigned)(ix + 1) < 160u)
                    fma4(acc, w11, ld4bf(&vg[(size_t)((iy + 1) * 160 + ix + 1) * 128]));
            }
        }
        Xb[px * 68 + lane * 2] = pk(acc.x, acc.y);
        Xb[px * 68 + lane * 2 + 1] = pk(acc.z, acc.w);
    }
    __syncthreads();
    int wm = wrp & 1, wn = wrp >> 1;
    int gid = lane >> 2, tig = lane & 3;
    float c[2][4][4];
#pragma unroll
    for (int nt = 0; nt < 4; nt++) {
        int o = wn * 16 + (nt & 1) * 8 + (nt >> 1) * 64 + 2 * tig;
        float b0 = Bo[o], b1 = Bo[o + 1];
#pragma unroll
        for (int mt = 0; mt < 2; mt++) {
            c[mt][nt][0] = b0; c[mt][nt][1] = b1;
            c[mt][nt][2] = b0; c[mt][nt][3] = b1;
        }
    }
#pragma unroll
    for (int kw = 0; kw < 64; kw += 8) {
        uint32_t A[2][4];
#pragma unroll
        for (int mt = 0; mt < 2; mt++) {
            int r = wm * 32 + mt * 16 + gid;
            A[mt][0] = Xb[r * 68 + kw + tig];
            A[mt][1] = Xb[(r + 8) * 68 + kw + tig];
            A[mt][2] = Xb[r * 68 + kw + 4 + tig];
            A[mt][3] = Xb[(r + 8) * 68 + kw + 4 + tig];
        }
#pragma unroll
        for (int nt = 0; nt < 4; nt++) {
            int n = wn * 16 + (nt & 1) * 8 + (nt >> 1) * 64 + gid;
            uint32_t Bf[2];
            Bf[0] = Wb[n * 68 + kw + tig];
            Bf[1] = Wb[n * 68 + kw + 4 + tig];
#pragma unroll
            for (int mt = 0; mt < 2; mt++) mma_bf16(c[mt][nt], A[mt], Bf);
        }
    }
#pragma unroll
    for (int mt = 0; mt < 2; mt++) {
        size_t r0 = base + wm * 32 + mt * 16 + gid;
#pragma unroll
        for (int ntp = 0; ntp < 2; ntp++) {
            int o = wn * 16 + ntp * 8 + 2 * tig;
            *(float2*)&g_f[r0 * 64 + o] =
                make_float2(c[mt][ntp][0] * c[mt][ntp + 2][0], c[mt][ntp][1] * c[mt][ntp + 2][1]);
            *(float2*)&g_f[(r0 + 8) * 64 + o] =
                make_float2(c[mt][ntp][2] * c[mt][ntp + 2][2], c[mt][ntp][3] * c[mt][ntp + 2][3]);
        }
    }
}

// ------------------------- pooling partials -------------------------
__global__ void __launch_bounds__(256) k_pool() {
    __shared__ float sh[256];
    int img = blockIdx.x >> 4, seg = blockIdx.x & 15;
    int tid = threadIdx.x;
    int c = tid & 63, q = tid >> 6;
    const float* fp = g_f + ((size_t)img * HW + seg * 1600) * 64;
    float s = 0.f;
    for (int n = 0; n < 400; n++) s += fp[(size_t)(q + 4 * n) * 64 + c];
    sh[tid] = s;
    __syncthreads();
    if (tid < 64)
        g_part[(img * 16 + seg) * 64 + tid] = sh[tid] + sh[tid + 64] + sh[tid + 128] + sh[tid + 192];
}

// ------------------------- finish pooling + SCA projection -------------------------
__global__ void __launch_bounds__(256) k_sca(const float* __restrict__ sw, const float* __restrict__ sb) {
    __shared__ float shp[256];
    int tid = threadIdx.x;
    int b = tid >> 7, c = tid & 127;
    int img = (c < 64) ? b : (2 + b);
    int cc = c & 63;
    float s = 0.f;
    for (int seg = 0; seg < 16; seg++) s += g_part[(img * 16 + seg) * 64 + cc];
    shp[tid] = s * (1.f / (float)HW);
    __syncthreads();
    float acc = __ldg(&sb[c]);
    for (int k = 0; k < 128; k++) acc += shp[b * 128 + k] * __ldg(&sw[c * 128 + k]);
    g_s[tid] = acc;
}

// ------------------------- SCA-folded conv3 + dual residual -> g_y -------------------------
__global__ void __launch_bounds__(256) k_conv3_y(const float* __restrict__ W3,
                                                 const float* __restrict__ B3,
                                                 const float* __restrict__ beta,
                                                 const float* __restrict__ x_l,
                                                 const float* __restrict__ x_r) {
    extern __shared__ float sm[];
    float* Fs = sm;              // 64*132
    float* W3s = sm + 64 * 132;  // 64*128 (scale-folded)
    int tid = threadIdx.x;
    int base = blockIdx.x * 64;
    int b = base / HW;
    int pos = base - b * HW;
    for (int i = tid; i < 64 * 128; i += 256) {
        int p = i >> 7, o = i & 127;
        float v = (o < 64) ? g_f[((size_t)b * HW + pos + p) * 64 + o]
                           : g_f[((size_t)(2 + b) * HW + pos + p) * 64 + (o - 64)];
        Fs[p * 132 + o] = v;
    }
    for (int i = tid; i < 64 * 128; i += 256) {
        int o = i & 127;
        W3s[i] = W3[i] * g_s[b * 128 + o];
    }
    __syncthreads();
    int pr = tid & 15, og = tid >> 4;
    float acc[4][4];
#pragma unroll
    for (int j = 0; j < 4; j++) {
        float bv = B3[og * 4 + j];
#pragma unroll
        for (int i = 0; i < 4; i++) acc[i][j] = bv;
    }
#pragma unroll 4
    for (int k = 0; k < 128; k += 4) {
        float4 xv[4];
#pragma unroll
        for (int i = 0; i < 4; i++) xv[i] = *(const float4*)&Fs[(pr + 16 * i) * 132 + k];
#pragma unroll
        for (int j = 0; j < 4; j++) {
            float4 wv = *(const float4*)&W3s[(og * 4 + j) * 128 + k];
#pragma unroll
            for (int i = 0; i < 4; i++)
                acc[i][j] += xv[i].x * wv.x + xv[i].y * wv.y + xv[i].z * wv.z + xv[i].w * wv.w;
        }
    }
#pragma unroll
    for (int i = 0; i < 4; i++) {
        int p = pr + 16 * i;
#pragma unroll
        for (int j = 0; j < 4; j++) {
            int jj = og * 4 + j;
            float bt = __ldg(&beta[jj]);
            float x3 = acc[i][j] * bt;
            float xl = x_l[((size_t)b * 64 + jj) * HW + pos + p];
            float xr = x_r[((size_t)b * 64 + jj) * HW + pos + p];
            g_y[(size_t)(base + p) * 128 + jj] = xl + x3;
            g_y[(size_t)(base + p) * 128 + 64 + jj] = xr + x3;
        }
    }
}

// ------------------------- LN2(128ch) + conv4 (bf16 mma) + gate -> g_zg -------------------------
__global__ void __launch_bounds__(256) k_ln2c4(const float* __restrict__ g2,
                                               const float* __restrict__ W4,
                                               const float* __restrict__ B4) {
    extern __shared__ float sm[];
    float* Yf = sm;                                 // 64*132 fp32
    uint32_t* Yb = (uint32_t*)(sm + 64 * 132);      // 64*68 words
    uint32_t* Wb = Yb + 64 * 68;                    // 128*68 words
    float* mr = (float*)(Wb + 128 * 68);            // 128
    int tid = threadIdx.x;
    int base = blockIdx.x * 64;
    for (int i = tid; i < 64 * 128; i += 256) {
        int p = i >> 7, c = i & 127;
        Yf[p * 132 + c] = g_y[(size_t)(base + p) * 128 + c];
    }
    for (int i = tid; i < 4096; i += 256) {
        int row = i >> 5, q = i & 31;
        float4 v = *(const float4*)&W4[row * 128 + q * 4];
        Wb[row * 68 + q * 2] = pk(v.x, v.y);
        Wb[row * 68 + q * 2 + 1] = pk(v.z, v.w);
    }
    __syncthreads();
    if (tid < 64) {
        float s = 0.f, sq = 0.f;
        for (int c = 0; c < 128; c++) { float v = Yf[tid * 132 + c]; s += v; sq += v * v; }
        float m = s * (1.f / 128.f);
        float var = sq * (1.f / 128.f) - m * m;
        mr[tid] = m; mr[64 + tid] = rsqrtf(var + 1e-5f);
    }
    __syncthreads();
    for (int i = tid; i < 64 * 64; i += 256) {
        int p = i >> 6, q = i & 63;
        int k0 = q * 2;
        float f0 = (Yf[p * 132 + k0] - mr[p]) * mr[64 + p] * __ldg(&g2[k0]);
        float f1 = (Yf[p * 132 + k0 + 1] - mr[p]) * mr[64 + p] * __ldg(&g2[k0 + 1]);
        Yb[p * 68 + q] = pk(f0, f1);
    }
    __syncthreads();
    int wid = tid >> 5, lane = tid & 31;
    int wm = wid & 1, wn = wid >> 1;
    int gid = lane >> 2, tig = lane & 3;
    float c[2][4][4];
#pragma unroll
    for (int nt = 0; nt < 4; nt++) {
        int o = wn * 16 + (nt & 1) * 8 + (nt >> 1) * 64 + 2 * tig;
        float b0 = B4[o], b1 = B4[o + 1];
#pragma unroll
        for (int mt = 0; mt < 2; mt++) {
            c[mt][nt][0] = b0; c[mt][nt][1] = b1;
            c[mt][nt][2] = b0; c[mt][nt][3] = b1;
        }
    }
#pragma unroll
    for (int kw = 0; kw < 64; kw += 8) {
        uint32_t A[2][4];
#pragma unroll
        for (int mt = 0; mt < 2; mt++) {
            int r = wm * 32 + mt * 16 + gid;
            A[mt][0] = Yb[r * 68 + kw + tig];
            A[mt][1] = Yb[(r + 8) * 68 + kw + tig];
            A[mt][2] = Yb[r * 68 + kw + 4 + tig];
            A[mt][3] = Yb[(r + 8) * 68 + kw + 4 + tig];
        }
#pragma unroll
        for (int nt = 0; nt < 4; nt++) {
            int n = wn * 16 + (nt & 1) * 8 + (nt >> 1) * 64 + gid;
            uint32_t Bf[2];
            Bf[0] = Wb[n * 68 + kw + tig];
            Bf[1] = Wb[n * 68 + kw + 4 + tig];
#pragma unroll
            for (int mt = 0; mt < 2; mt++) mma_bf16(c[mt][nt], A[mt], Bf);
        }
    }
#pragma unroll
    for (int mt = 0; mt < 2; mt++) {
        size_t r0 = base + wm * 32 + mt * 16 + gid;
#pragma unroll
        for (int ntp = 0; ntp < 2; ntp++) {
            int o = wn * 16 + ntp * 8 + 2 * tig;
            *(float2*)&g_zg[r0 * 64 + o] =
                make_float2(c[mt][ntp][0] * c[mt][ntp + 2][0], c[mt][ntp][1] * c[mt][ntp + 2][1]);
            *(float2*)&g_zg[(r0 + 8) * 64 + o] =
                make_float2(c[mt][ntp][2] * c[mt][ntp + 2][2], c[mt][ntp][3] * c[mt][ntp + 2][3]);
        }
    }
}

// ------------------------- conv5 + final residuals, NCHW outputs -------------------------
__global__ void __launch_bounds__(256) k_c5out(const float* __restrict__ W5,
                                               const float* __restrict__ B5,
                                               const float* __restrict__ gamma,
                                               float* __restrict__ out) {
    extern __shared__ float sm[];
    float* Zs = sm;                    // 64*68
    float* W5s = sm + 64 * 68;         // 64*64
    float* Ys = W5s + 64 * 64;         // 64*132
    int tid = threadIdx.x;
    int base = blockIdx.x * 64;
    int b = base / HW;
    int pos = base - b * HW;
    for (int i = tid; i < 64 * 64; i += 256) {
        int p = i >> 6, k = i & 63;
        Zs[p * 68 + k] = g_zg[(size_t)(base + p) * 64 + k];
    }
    for (int i = tid; i < 64 * 64; i += 256) W5s[i] = W5[i];
    for (int i = tid; i < 64 * 128; i += 256) {
        int p = i >> 7, c = i & 127;
        Ys[p * 132 + c] = g_y[(size_t)(base + p) * 128 + c];
    }
    __syncthreads();
    int pr = tid & 15, og = tid >> 4;
    float acc[4][4];
#pragma unroll
    for (int j = 0; j < 4; j++) {
        float bv = B5[og * 4 + j];
#pragma unroll
        for (int i = 0; i < 4; i++) acc[i][j] = bv;
    }
#pragma unroll 4
    for (int k = 0; k < 64; k += 4) {
        float4 xv[4];
#pragma unroll
        for (int i = 0; i < 4; i++) xv[i] = *(const float4*)&Zs[(pr + 16 * i) * 68 + k];
#pragma unroll
        for (int j = 0; j < 4; j++) {
            float4 wv = *(const float4*)&W5s[(og * 4 + j) * 64 + k];
#pragma unroll
            for (int i = 0; i < 4; i++)
                acc[i][j] += xv[i].x * wv.x + xv[i].y * wv.y + xv[i].z * wv.z + xv[i].w * wv.w;
        }
    }
    const size_t HALF = (size_t)2 * 64 * HW;
#pragma unroll
    for (int i = 0; i < 4; i++) {
        int p = pr + 16 * i;
#pragma unroll
        for (int j = 0; j < 4; j++) {
            int cc = og * 4 + j;
            float z = acc[i][j] * __ldg(&gamma[cc]);
            size_t o = ((size_t)b * 64 + cc) * HW + pos + p;
            out[o] = Ys[p * 132 + cc] + z;
            out[HALF + o] = Ys[p * 132 + 64 + cc] + z;
        }
    }
}

// ------------------------- host -------------------------
extern "C" void kernel_launch(void* const* d_in, const int* in_sizes, int n_in,
                              void* d_out, int out_size) {
    const float* x_l     = (const float*)d_in[0];
    const float* x_r     = (const float*)d_in[1];
    const float* ln1_g   = (const float*)d_in[2];
    const float* pw1_w   = (const float*)d_in[3];
    const float* pw1_b   = (const float*)d_in[4];
    const float* val_w   = (const float*)d_in[5];
    const float* val_b   = (const float*)d_in[6];
    const float* dwc_w   = (const float*)d_in[7];
    const float* dwc_b   = (const float*)d_in[8];
    const float* om_w    = (const float*)d_in[9];
    const float* om_b    = (const float*)d_in[10];
    const float* outp_w  = (const float*)d_in[11];
    const float* outp_b  = (const float*)d_in[12];
    const float* sca_w   = (const float*)d_in[13];
    const float* sca_b   = (const float*)d_in[14];
    const float* conv3_w = (const float*)d_in[15];
    const float* conv3_b = (const float*)d_in[16];
    const float* norm2_g = (const float*)d_in[17];
    const float* conv4_w = (const float*)d_in[18];
    const float* conv4_b = (const float*)d_in[19];
    const float* conv5_w = (const float*)d_in[20];
    const float* conv5_b = (const float*)d_in[21];
    const float* beta    = (const float*)d_in[22];
    const float* gamma   = (const float*)d_in[23];
    float* out = (float*)d_out;

    __nv_bfloat16 *ph, *pv, *pdw;
    float* pom;
    cudaGetSymbolAddress((void**)&ph, g_h);
    cudaGetSymbolAddress((void**)&pv, g_v);
    cudaGetSymbolAddress((void**)&pdw, g_dw);
    cudaGetSymbolAddress((void**)&pom, g_om);

    const int SM_LNPW1 = (64 * 68 + 64 * 36 + 128 * 36 + 128) * 4;
    const int SM_TG    = (2 * 128 * 68) * 4;
    const int SM_SOUT  = (128 * 68 + 64 * 68 + 8 * 112) * 4;
    const int SM_C3    = (64 * 132 + 64 * 128) * 4;
    const int SM_LN2   = (64 * 132 + 64 * 68 + 128 * 68 + 128) * 4;
    const int SM_C5    = (64 * 68 + 64 * 64 + 64 * 132) * 4;

    cudaFuncSetAttribute(k_ln_pw1,        cudaFuncAttributeMaxDynamicSharedMemorySize, SM_LNPW1);
    cudaFuncSetAttribute((k_tg<128, true>),  cudaFuncAttributeMaxDynamicSharedMemorySize, SM_TG);
    cudaFuncSetAttribute((k_tg<112, false>), cudaFuncAttributeMaxDynamicSharedMemorySize, SM_TG);
    cudaFuncSetAttribute(k_souter,        cudaFuncAttributeMaxDynamicSharedMemorySize, SM_SOUT);
    cudaFuncSetAttribute(k_conv3_y,       cudaFuncAttributeMaxDynamicSharedMemorySize, SM_C3);
    cudaFuncSetAttribute(k_ln2c4,         cudaFuncAttributeMaxDynamicSharedMemorySize, SM_LN2);
    cudaFuncSetAttribute(k_c5out,         cudaFuncAttributeMaxDynamicSharedMemorySize, SM_C5);

    k_ln_pw1         <<<P4 / 64, 256, SM_LNPW1>>>(x_l, x_r, ln1_g, pw1_w, pw1_b);
    k_tg<128, true>  <<<P4 / 128, 256, SM_TG>>>(ph, pv, val_w, val_b);     // value proj (bf16 out)
    k_dwc4           <<<P4 * 128 / (256 * 4), 256>>>(dwc_w, dwc_b);
    k_tg<112, false> <<<P4 / 128, 256, SM_TG>>>(pdw, pom, om_w, om_b);     // offset/mask proj
    k_souter         <<<P4 / 64, 256, SM_SOUT>>>(outp_w, outp_b);
    k_pool           <<<64, 256>>>();
    k_sca            <<<1, 256>>>(sca_w, sca_b);
    k_conv3_y        <<<P2 / 64, 256, SM_C3>>>(conv3_w, conv3_b, beta, x_l, x_r);
    k_ln2c4          <<<P2 / 64, 256, SM_LN2>>>(norm2_g, conv4_w, conv4_b);
    k_c5out          <<<P2 / 64, 256, SM_C5>>>(conv5_w, conv5_b, gamma, out);
}

// round 8
// speedup vs baseline: 2.3707x; 1.0022x over previous
#include <cuda_runtime.h>
#include <cuda_bf16.h>
#include <cstdint>

#define HW 25600
#define P4 102400   // 4 images * HW  (img 0,1 = x_l b0,b1 ; img 2,3 = x_r b0,b1)
#define P2 51200    // 2 batches * HW

// ------------------------- scratch (__device__ globals) -------------------------
__device__ __nv_bfloat16 g_h[(size_t)P4 * 128];   // LN1+pw1 out, NHWC (bf16)
__device__ __nv_bfloat16 g_v[(size_t)P4 * 128];   // value proj (bf16)
__device__ __nv_bfloat16 g_dw[(size_t)P4 * 128];  // depthwise conv out (bf16)
__device__ __nv_bfloat16 g_om[(size_t)P4 * 112];  // offset/mask proj (bf16)
__device__ __nv_bfloat16 g_f[(size_t)P4 * 64];    // gated branch features (bf16)
__device__ float g_y[(size_t)P2 * 128];           // [y_l(64) ; y_r(64)] NHWC per batch
__device__ float g_zg[(size_t)P2 * 64];           // gated conv4 output
__device__ float g_part[64 * 64];                 // pooling partials
__device__ float g_s[256];                        // SCA scale s[b][128]
__device__ __nv_bfloat16 g_wp[71680];             // packed bf16 weights

// packed-weight segment offsets (elements)
#define OFF_PW1   0
#define OFF_VAL   8192
#define OFF_OM    24576
#define OFF_OUTP  38912
#define OFF_C4    55296

// ------------------------- bf16 helpers -------------------------
__device__ __forceinline__ uint32_t pk(float a, float b) {
    __nv_bfloat162 t = __floats2bfloat162_rn(a, b);
    return *reinterpret_cast<uint32_t*>(&t);
}
__device__ __forceinline__ float2 upk(uint32_t u) {
    __nv_bfloat162 t = *reinterpret_cast<__nv_bfloat162*>(&u);
    return __bfloat1622float2(t);
}
__device__ __forceinline__ float4 ld4bf(const __nv_bfloat16* p) {
    uint2 u = *(const uint2*)p;
    float2 fa = upk(u.x), fb = upk(u.y);
    return make_float4(fa.x, fa.y, fb.x, fb.y);
}
__device__ __forceinline__ void mma_bf16(float* c, const uint32_t* a, const uint32_t* b) {
    asm volatile(
        "mma.sync.aligned.m16n8k16.row.col.f32.bf16.bf16.f32 "
        "{%0,%1,%2,%3}, {%4,%5,%6,%7}, {%8,%9}, {%0,%1,%2,%3};"
        : "+f"(c[0]), "+f"(c[1]), "+f"(c[2]), "+f"(c[3])
        : "r"(a[0]), "r"(a[1]), "r"(a[2]), "r"(a[3]), "r"(b[0]), "r"(b[1]));
}

// ------------------------- weight pack kernel -------------------------
__global__ void __launch_bounds__(256) k_pack(const float* __restrict__ pw1,
                                              const float* __restrict__ val,
                                              const float* __restrict__ om,
                                              const float* __restrict__ outp,
                                              const float* __restrict__ c4) {
    int i = blockIdx.x * 256 + threadIdx.x;
    if (i >= 71680) return;
    float v;
    if (i < OFF_VAL)       v = pw1[i - OFF_PW1];
    else if (i < OFF_OM)   v = val[i - OFF_VAL];
    else if (i < OFF_OUTP) v = om[i - OFF_OM];
    else if (i < OFF_C4)   v = outp[i - OFF_OUTP];
    else                   v = c4[i - OFF_C4];
    g_wp[i] = __float2bfloat16_rn(v);
}

// ------------------------- kernel 1: LN + pw1 + val GEMM fused -------------------------
__global__ void __launch_bounds__(256) k_lnpw1v(const float* __restrict__ x_l,
                                                const float* __restrict__ x_r,
                                                const float* __restrict__ g1,
                                                const float* __restrict__ B1,
                                                const float* __restrict__ Bv) {
    extern __shared__ float sm[];
    float* Xf = sm;                            // 64*68 fp32
    float* mr = Xf + 64 * 68;                  // 128
    uint32_t* Xb = (uint32_t*)(mr + 128);      // 64*36 (bf16 pairs, K=64)
    uint32_t* Wb = Xb + 64 * 36;               // 128*36 (pw1 weights)
    uint32_t* Wv = Wb + 128 * 36;              // 128*68 (val weights, K=128)
    uint32_t* Hb = Wv + 128 * 68;              // 64*68  (h tile bf16)
    int tid = threadIdx.x;
    int base = blockIdx.x * 64;
    int img = base / HW;
    int pos = base - img * HW;
    const float* xp = (img < 2) ? (x_l + (size_t)img * HW * 64)
                                : (x_r + (size_t)(img - 2) * HW * 64);
    for (int i = tid; i < 64 * 64; i += 256) {
        int c = i >> 6, p = i & 63;
        Xf[p * 68 + c] = xp[(size_t)c * HW + pos + p];
    }
    // pw1 weights: 128 rows x 64 bf16 = 128 x 8 uint4
    const uint4* Wp1 = (const uint4*)(g_wp + OFF_PW1);
    for (int i = tid; i < 1024; i += 256) {
        int row = i >> 3, q = i & 7;
        uint4 u = __ldg(&Wp1[row * 8 + q]);
        Wb[row * 36 + q * 4]     = u.x;
        Wb[row * 36 + q * 4 + 1] = u.y;
        Wb[row * 36 + q * 4 + 2] = u.z;
        Wb[row * 36 + q * 4 + 3] = u.w;
    }
    // val weights: 128 rows x 128 bf16 = 128 x 16 uint4
    const uint4* Wpv = (const uint4*)(g_wp + OFF_VAL);
    for (int i = tid; i < 2048; i += 256) {
        int row = i >> 4, q = i & 15;
        uint4 u = __ldg(&Wpv[row * 16 + q]);
        Wv[row * 68 + q * 4]     = u.x;
        Wv[row * 68 + q * 4 + 1] = u.y;
        Wv[row * 68 + q * 4 + 2] = u.z;
        Wv[row * 68 + q * 4 + 3] = u.w;
    }
    __syncthreads();
    if (tid < 64) {
        float s = 0.f, sq = 0.f;
        for (int c = 0; c < 64; c++) { float v = Xf[tid * 68 + c]; s += v; sq += v * v; }
        float m = s * (1.f / 64.f);
        float var = sq * (1.f / 64.f) - m * m;
        mr[tid] = m; mr[64 + tid] = rsqrtf(var + 1e-5f);
    }
    __syncthreads();
    for (int i = tid; i < 64 * 32; i += 256) {
        int p = i >> 5, q = i & 31;
        int k0 = q * 2;
        float f0 = (Xf[p * 68 + k0] - mr[p]) * mr[64 + p] * __ldg(&g1[k0]);
        float f1 = (Xf[p * 68 + k0 + 1] - mr[p]) * mr[64 + p] * __ldg(&g1[k0 + 1]);
        Xb[p * 36 + q] = pk(f0, f1);
    }
    __syncthreads();
    int wid = tid >> 5, lane = tid & 31;
    int wm = wid & 1, wn = wid >> 1;             // 2 m-warps x 4 n-warps (32 cols)
    int gid = lane >> 2, tig = lane & 3;
    // ---- phase 1: h = LN(x) @ pw1^T + b1 ----
    {
        float c[2][4][4];
#pragma unroll
        for (int nt = 0; nt < 4; nt++) {
            int o = wn * 32 + nt * 8 + 2 * tig;
            float b0 = B1[o], b1 = B1[o + 1];
#pragma unroll
            for (int mt = 0; mt < 2; mt++) {
                c[mt][nt][0] = b0; c[mt][nt][1] = b1;
                c[mt][nt][2] = b0; c[mt][nt][3] = b1;
            }
        }
#pragma unroll
        for (int kw = 0; kw < 32; kw += 8) {
            uint32_t A[2][4];
#pragma unroll
            for (int mt = 0; mt < 2; mt++) {
                int r = wm * 32 + mt * 16 + gid;
                A[mt][0] = Xb[r * 36 + kw + tig];
                A[mt][1] = Xb[(r + 8) * 36 + kw + tig];
                A[mt][2] = Xb[r * 36 + kw + 4 + tig];
                A[mt][3] = Xb[(r + 8) * 36 + kw + 4 + tig];
            }
#pragma unroll
            for (int nt = 0; nt < 4; nt++) {
                int n = wn * 32 + nt * 8 + gid;
                uint32_t Bf[2];
                Bf[0] = Wb[n * 36 + kw + tig];
                Bf[1] = Wb[n * 36 + kw + 4 + tig];
#pragma unroll
                for (int mt = 0; mt < 2; mt++) mma_bf16(c[mt][nt], A[mt], Bf);
            }
        }
        uint32_t* gh = (uint32_t*)g_h;
#pragma unroll
        for (int mt = 0; mt < 2; mt++) {
            int rl = wm * 32 + mt * 16 + gid;
            size_t r0 = base + rl;
#pragma unroll
            for (int nt = 0; nt < 4; nt++) {
                int o = wn * 32 + nt * 8 + 2 * tig;
                uint32_t w0 = pk(c[mt][nt][0], c[mt][nt][1]);
                uint32_t w1 = pk(c[mt][nt][2], c[mt][nt][3]);
                gh[r0 * 64 + o / 2] = w0;
                gh[(r0 + 8) * 64 + o / 2] = w1;
                Hb[rl * 68 + o / 2] = w0;
                Hb[(rl + 8) * 68 + o / 2] = w1;
            }
        }
    }
    __syncthreads();
    // ---- phase 2: v = h @ val^T + bv (K=128) ----
    {
        float c[2][4][4];
#pragma unroll
        for (int nt = 0; nt < 4; nt++) {
            int o = wn * 32 + nt * 8 + 2 * tig;
            float b0 = Bv[o], b1 = Bv[o + 1];
#pragma unroll
            for (int mt = 0; mt < 2; mt++) {
                c[mt][nt][0] = b0; c[mt][nt][1] = b1;
                c[mt][nt][2] = b0; c[mt][nt][3] = b1;
            }
        }
#pragma unroll
        for (int kw = 0; kw < 64; kw += 8) {
            uint32_t A[2][4];
#pragma unroll
            for (int mt = 0; mt < 2; mt++) {
                int r = wm * 32 + mt * 16 + gid;
                A[mt][0] = Hb[r * 68 + kw + tig];
                A[mt][1] = Hb[(r + 8) * 68 + kw + tig];
                A[mt][2] = Hb[r * 68 + kw + 4 + tig];
                A[mt][3] = Hb[(r + 8) * 68 + kw + 4 + tig];
            }
#pragma unroll
            for (int nt = 0; nt < 4; nt++) {
                int n = wn * 32 + nt * 8 + gid;
                uint32_t Bf[2];
                Bf[0] = Wv[n * 68 + kw + tig];
                Bf[1] = Wv[n * 68 + kw + 4 + tig];
#pragma unroll
                for (int mt = 0; mt < 2; mt++) mma_bf16(c[mt][nt], A[mt], Bf);
            }
        }
        uint32_t* gv = (uint32_t*)g_v;
#pragma unroll
        for (int mt = 0; mt < 2; mt++) {
            size_t r0 = base + wm * 32 + mt * 16 + gid;
#pragma unroll
            for (int nt = 0; nt < 4; nt++) {
                int o = wn * 32 + nt * 8 + 2 * tig;
                gv[r0 * 64 + o / 2] = pk(c[mt][nt][0], c[mt][nt][1]);
                gv[(r0 + 8) * 64 + o / 2] = pk(c[mt][nt][2], c[mt][nt][3]);
            }
        }
    }
}

// ------------------------- bf16 tensor GEMM (om): 128px x 112, K=128 -------------------------
__global__ void __launch_bounds__(256) k_tgom(const float* __restrict__ Bb) {
    const int N = 112;
    extern __shared__ uint32_t smu[];
    uint32_t* Xu = smu;              // 128*68 words
    uint32_t* Wu = smu + 128 * 68;   // 128*68 words (rows >= N zeroed)
    int tid = threadIdx.x;
    size_t base = (size_t)blockIdx.x * 128;
    const uint2* Xg = (const uint2*)g_dw;
    for (int i = tid; i < 4096; i += 256) {
        int row = i >> 5, q = i & 31;
        uint2 u = __ldg(&Xg[(base + row) * 32 + q]);
        Xu[row * 68 + q * 2] = u.x;
        Xu[row * 68 + q * 2 + 1] = u.y;
    }
    const uint4* Wg = (const uint4*)(g_wp + OFF_OM);
    for (int i = tid; i < 2048; i += 256) {
        int row = i >> 4, q = i & 15;
        uint4 u = make_uint4(0u, 0u, 0u, 0u);
        if (row < N) u = __ldg(&Wg[row * 16 + q]);
        Wu[row * 68 + q * 4]     = u.x;
        Wu[row * 68 + q * 4 + 1] = u.y;
        Wu[row * 68 + q * 4 + 2] = u.z;
        Wu[row * 68 + q * 4 + 3] = u.w;
    }
    __syncthreads();
    int wid = tid >> 5, lane = tid & 31;
    int wm = wid & 3, wn = wid >> 2;
    int gid = lane >> 2, tig = lane & 3;
    float c[2][8][4];
#pragma unroll
    for (int nt = 0; nt < 8; nt++) {
        int o = wn * 64 + nt * 8 + 2 * tig;
        float b0 = (o < N) ? Bb[o] : 0.f;
        float b1 = (o + 1 < N) ? Bb[o + 1] : 0.f;
#pragma unroll
        for (int mt = 0; mt < 2; mt++) {
            c[mt][nt][0] = b0; c[mt][nt][1] = b1;
            c[mt][nt][2] = b0; c[mt][nt][3] = b1;
        }
    }
#pragma unroll
    for (int kw = 0; kw < 64; kw += 8) {
        uint32_t A[2][4];
#pragma unroll
        for (int mt = 0; mt < 2; mt++) {
            int r = wm * 32 + mt * 16 + gid;
            A[mt][0] = Xu[r * 68 + kw + tig];
            A[mt][1] = Xu[(r + 8) * 68 + kw + tig];
            A[mt][2] = Xu[r * 68 + kw + 4 + tig];
            A[mt][3] = Xu[(r + 8) * 68 + kw + 4 + tig];
        }
        uint32_t Bf[8][2];
#pragma unroll
        for (int nt = 0; nt < 8; nt++) {
            int n = wn * 64 + nt * 8 + gid;
            Bf[nt][0] = Wu[n * 68 + kw + tig];
            Bf[nt][1] = Wu[n * 68 + kw + 4 + tig];
        }
#pragma unroll
        for (int mt = 0; mt < 2; mt++)
#pragma unroll
            for (int nt = 0; nt < 8; nt++)
                mma_bf16(c[mt][nt], A[mt], Bf[nt]);
    }
    uint32_t* Yu = (uint32_t*)g_om;
#pragma unroll
    for (int mt = 0; mt < 2; mt++) {
        size_t r0 = base + wm * 32 + mt * 16 + gid;
#pragma unroll
        for (int nt = 0; nt < 8; nt++) {
            int o = wn * 64 + nt * 8 + 2 * tig;
            if (o < N) {
                Yu[r0 * 56 + o / 2] = pk(c[mt][nt][0], c[mt][nt][1]);
                Yu[(r0 + 8) * 56 + o / 2] = pk(c[mt][nt][2], c[mt][nt][3]);
            }
        }
    }
}

// ------------------------- depthwise 3x3, 4 px per thread (bf16 in/out) -------------------------
__global__ void __launch_bounds__(256) k_dwc4(const float* __restrict__ Wd,
                                              const float* __restrict__ Bd) {
    int linear = blockIdx.x * 256 + threadIdx.x;
    int c = linear & 127;
    int pq = linear >> 7;
    int img = pq / 6400;
    int q = pq - img * 6400;
    int h = q / 40;
    int w4 = (q - h * 40) * 4;
    float wt[9];
#pragma unroll
    for (int t = 0; t < 9; t++) wt[t] = __ldg(&Wd[t * 128 + c]);
    float a[4];
    float bv = __ldg(&Bd[c]);
#pragma unroll
    for (int j = 0; j < 4; j++) a[j] = bv;
    const __nv_bfloat16* basep = g_h + (size_t)img * HW * 128 + c;
#pragma unroll
    for (int dy = 0; dy < 3; dy++) {
        int y = h + dy - 1;
        if ((unsigned)y >= 160u) continue;
        const __nv_bfloat16* row = basep + (size_t)y * 160 * 128;
#pragma unroll
        for (int t = 0; t < 6; t++) {
            int x = w4 + t - 1;
            if ((unsigned)x >= 160u) continue;
            float v = __bfloat162float(row[(size_t)x * 128]);
#pragma unroll
            for (int j = 0; j < 4; j++) {
                int dx = t - j;
                if (dx >= 0 && dx <= 2) a[j] += v * wt[dy * 3 + dx];
            }
        }
    }
    size_t o = ((size_t)pq * 4) * 128 + c;
#pragma unroll
    for (int j = 0; j < 4; j++) g_dw[o + (size_t)j * 128] = __float2bfloat16_rn(a[j]);
}

// ------------------------- fused: deformable sample + outp GEMM (bf16) + SimpleGate -------------------------
__device__ __forceinline__ void fma4(float4& a, float w, const float4 v) {
    a.x += w * v.x; a.y += w * v.y; a.z += w * v.z; a.w += w * v.w;
}

__global__ void __launch_bounds__(256) k_souter(const float* __restrict__ Bo) {
    extern __shared__ uint32_t smu[];
    uint32_t* Wb = smu;                         // 128*68 words
    uint32_t* Xb = smu + 128 * 68;              // 64*68 words
    float* OMs = (float*)(Xb + 64 * 68);        // 8 warps * 112
    int tid = threadIdx.x;
    int base = blockIdx.x * 64;
    int img = base / HW;
    int pbase = base - img * HW;
    const uint4* Wg = (const uint4*)(g_wp + OFF_OUTP);
    for (int i = tid; i < 2048; i += 256) {
        int row = i >> 4, q = i & 15;
        uint4 u = __ldg(&Wg[row * 16 + q]);
        Wb[row * 68 + q * 4]     = u.x;
        Wb[row * 68 + q * 4 + 1] = u.y;
        Wb[row * 68 + q * 4 + 2] = u.z;
        Wb[row * 68 + q * 4 + 3] = u.w;
    }
    int wrp = tid >> 5, lane = tid & 31;
    int g = lane >> 3, c4 = lane & 7;
    const __nv_bfloat16* vg = g_v + (size_t)img * HW * 128 + g * 32 + c4 * 4;
    float* oms = OMs + wrp * 112;
    for (int p8 = 0; p8 < 8; p8++) {
        int px = wrp * 8 + p8;
        int pos = pbase + px;
        int hh = pos / 160, ww = pos - hh * 160;
        const uint32_t* omu = (const uint32_t*)(g_om + ((size_t)img * HW + pos) * 112);
        __syncwarp();
        {
            float2 f = upk(omu[lane]);
            oms[2 * lane] = f.x; oms[2 * lane + 1] = f.y;
            if (lane < 24) {
                float2 f2 = upk(omu[32 + lane]);
                oms[64 + 2 * lane] = f2.x; oms[64 + 2 * lane + 1] = f2.y;
            }
        }
        __syncwarp();
        float4 acc = make_float4(0.f, 0.f, 0.f, 0.f);
#pragma unroll
        for (int k = 0; k < 9; k++) {
            float ox = oms[g * 27 + k * 3 + 0];
            float oy = oms[g * 27 + k * 3 + 1];
            float mk = oms[g * 27 + k * 3 + 2];
            float fx = (float)(ww + (k % 3) - 1) + ox;
            float fy = (float)(hh + (k / 3) - 1) + oy;
            float x0f = floorf(fx), y0f = floorf(fy);
            float tx = fx - x0f, ty = fy - y0f;
            int ix = (int)x0f, iy = (int)y0f;
            float w00 = (1.f - tx) * (1.f - ty) * mk;
            float w01 = tx * (1.f - ty) * mk;
            float w10 = (1.f - tx) * ty * mk;
            float w11 = tx * ty * mk;
            if ((unsigned)iy < 160u) {
                if ((unsigned)ix < 160u)
                    fma4(acc, w00, ld4bf(&vg[(size_t)(iy * 160 + ix) * 128]));
                if ((unsigned)(ix + 1) < 160u)
                    fma4(acc, w01, ld4bf(&vg[(size_t)(iy * 160 + ix + 1) * 128]));
            }
            if ((unsigned)(iy + 1) < 160u) {
                if ((unsigned)ix < 160u)
                    fma4(acc, w10, ld4bf(&vg[(size_t)((iy + 1) * 160 + ix) * 128]));
                if ((unsigned)(ix + 1) < 160u)
                    fma4(acc, w11, ld4bf(&vg[(size_t)((iy + 1) * 160 + ix + 1) * 128]));
            }
        }
        Xb[px * 68 + lane * 2] = pk(acc.x, acc.y);
        Xb[px * 68 + lane * 2 + 1] = pk(acc.z, acc.w);
    }
    __syncthreads();
    int wm = wrp & 1, wn = wrp >> 1;
    int gid = lane >> 2, tig = lane & 3;
    float c[2][4][4];
#pragma unroll
    for (int nt = 0; nt < 4; nt++) {
        int o = wn * 16 + (nt & 1) * 8 + (nt >> 1) * 64 + 2 * tig;
        float b0 = Bo[o], b1 = Bo[o + 1];
#pragma unroll
        for (int mt = 0; mt < 2; mt++) {
            c[mt][nt][0] = b0; c[mt][nt][1] = b1;
            c[mt][nt][2] = b0; c[mt][nt][3] = b1;
        }
    }
#pragma unroll
    for (int kw = 0; kw < 64; kw += 8) {
        uint32_t A[2][4];
#pragma unroll
        for (int mt = 0; mt < 2; mt++) {
            int r = wm * 32 + mt * 16 + gid;
            A[mt][0] = Xb[r * 68 + kw + tig];
            A[mt][1] = Xb[(r + 8) * 68 + kw + tig];
            A[mt][2] = Xb[r * 68 + kw + 4 + tig];
            A[mt][3] = Xb[(r + 8) * 68 + kw + 4 + tig];
        }
#pragma unroll
        for (int nt = 0; nt < 4; nt++) {
            int n = wn * 16 + (nt & 1) * 8 + (nt >> 1) * 64 + gid;
            uint32_t Bf[2];
            Bf[0] = Wb[n * 68 + kw + tig];
            Bf[1] = Wb[n * 68 + kw + 4 + tig];
#pragma unroll
            for (int mt = 0; mt < 2; mt++) mma_bf16(c[mt][nt], A[mt], Bf);
        }
    }
    uint32_t* gf = (uint32_t*)g_f;
#pragma unroll
    for (int mt = 0; mt < 2; mt++) {
        size_t r0 = base + wm * 32 + mt * 16 + gid;
#pragma unroll
        for (int ntp = 0; ntp < 2; ntp++) {
            int o = wn * 16 + ntp * 8 + 2 * tig;
            gf[r0 * 32 + o / 2] =
                pk(c[mt][ntp][0] * c[mt][ntp + 2][0], c[mt][ntp][1] * c[mt][ntp + 2][1]);
            gf[(r0 + 8) * 32 + o / 2] =
                pk(c[mt][ntp][2] * c[mt][ntp + 2][2], c[mt][ntp][3] * c[mt][ntp + 2][3]);
        }
    }
}

// ------------------------- pooling partials (bf16 input) -------------------------
__global__ void __launch_bounds__(256) k_pool() {
    __shared__ float sh[512];
    int img = blockIdx.x >> 4, seg = blockIdx.x & 15;
    int tid = threadIdx.x;
    int word = tid & 31, q = tid >> 5;     // q in 0..7
    const uint32_t* fp = (const uint32_t*)g_f + ((size_t)img * HW + seg * 1600) * 32;
    float s0 = 0.f, s1 = 0.f;
    for (int n = 0; n < 200; n++) {
        float2 f = upk(fp[(size_t)(q + 8 * n) * 32 + word]);
        s0 += f.x; s1 += f.y;
    }
    sh[tid] = s0; sh[256 + tid] = s1;
    __syncthreads();
    if (tid < 32) {
        float a0 = 0.f, a1 = 0.f;
        for (int r = 0; r < 8; r++) { a0 += sh[r * 32 + tid]; a1 += sh[256 + r * 32 + tid]; }
        g_part[(img * 16 + seg) * 64 + 2 * tid] = a0;
        g_part[(img * 16 + seg) * 64 + 2 * tid + 1] = a1;
    }
}

// ------------------------- finish pooling + SCA projection -------------------------
__global__ void __launch_bounds__(256) k_sca(const float* __restrict__ sw, const float* __restrict__ sb) {
    __shared__ float shp[256];
    int tid = threadIdx.x;
    int b = tid >> 7, c = tid & 127;
    int img = (c < 64) ? b : (2 + b);
    int cc = c & 63;
    float s = 0.f;
    for (int seg = 0; seg < 16; seg++) s += g_part[(img * 16 + seg) * 64 + cc];
    shp[tid] = s * (1.f / (float)HW);
    __syncthreads();
    float acc = __ldg(&sb[c]);
    for (int k = 0; k < 128; k++) acc += shp[b * 128 + k] * __ldg(&sw[c * 128 + k]);
    g_s[tid] = acc;
}

// ------------------------- SCA-folded conv3 + dual residual -> g_y -------------------------
__global__ void __launch_bounds__(256) k_conv3_y(const float* __restrict__ W3,
                                                 const float* __restrict__ B3,
                                                 const float* __restrict__ beta,
                                                 const float* __restrict__ x_l,
                                                 const float* __restrict__ x_r) {
    extern __shared__ float sm[];
    float* Fs = sm;              // 64*132
    float* W3s = sm + 64 * 132;  // 64*128 (scale-folded)
    int tid = threadIdx.x;
    int base = blockIdx.x * 64;
    int b = base / HW;
    int pos = base - b * HW;
    const uint32_t* gf = (const uint32_t*)g_f;
    for (int i = tid; i < 64 * 64; i += 256) {
        int p = i >> 6, w = i & 63;
        int imgX = (w < 32) ? b : (2 + b);
        float2 f = upk(gf[((size_t)imgX * HW + pos + p) * 32 + (w & 31)]);
        Fs[p * 132 + 2 * w] = f.x;
        Fs[p * 132 + 2 * w + 1] = f.y;
    }
    for (int i = tid; i < 64 * 128; i += 256) {
        int o = i & 127;
        W3s[i] = W3[i] * g_s[b * 128 + o];
    }
    __syncthreads();
    int pr = tid & 15, og = tid >> 4;
    float acc[4][4];
#pragma unroll
    for (int j = 0; j < 4; j++) {
        float bv = B3[og * 4 + j];
#pragma unroll
        for (int i = 0; i < 4; i++) acc[i][j] = bv;
    }
#pragma unroll 4
    for (int k = 0; k < 128; k += 4) {
        float4 xv[4];
#pragma unroll
        for (int i = 0; i < 4; i++) xv[i] = *(const float4*)&Fs[(pr + 16 * i) * 132 + k];
#pragma unroll
        for (int j = 0; j < 4; j++) {
            float4 wv = *(const float4*)&W3s[(og * 4 + j) * 128 + k];
#pragma unroll
            for (int i = 0; i < 4; i++)
                acc[i][j] += xv[i].x * wv.x + xv[i].y * wv.y + xv[i].z * wv.z + xv[i].w * wv.w;
        }
    }
#pragma unroll
    for (int i = 0; i < 4; i++) {
        int p = pr + 16 * i;
#pragma unroll
        for (int j = 0; j < 4; j++) {
            int jj = og * 4 + j;
            float bt = __ldg(&beta[jj]);
            float x3 = acc[i][j] * bt;
            float xl = x_l[((size_t)b * 64 + jj) * HW + pos + p];
            float xr = x_r[((size_t)b * 64 + jj) * HW + pos + p];
            g_y[(size_t)(base + p) * 128 + jj] = xl + x3;
            g_y[(size_t)(base + p) * 128 + 64 + jj] = xr + x3;
        }
    }
}

// ------------------------- LN2(128ch) + conv4 (bf16 mma) + gate -> g_zg -------------------------
__global__ void __launch_bounds__(256) k_ln2c4(const float* __restrict__ g2,
                                               const float* __restrict__ B4) {
    extern __shared__ float sm[];
    float* Yf = sm;                                 // 64*132 fp32
    uint32_t* Yb = (uint32_t*)(sm + 64 * 132);      // 64*68 words
    uint32_t* Wb = Yb + 64 * 68;                    // 128*68 words
    float* mr = (float*)(Wb + 128 * 68);            // 128
    int tid = threadIdx.x;
    int base = blockIdx.x * 64;
    for (int i = tid; i < 64 * 128; i += 256) {
        int p = i >> 7, c = i & 127;
        Yf[p * 132 + c] = g_y[(size_t)(base + p) * 128 + c];
    }
    const uint4* Wg = (const uint4*)(g_wp + OFF_C4);
    for (int i = tid; i < 2048; i += 256) {
        int row = i >> 4, q = i & 15;
        uint4 u = __ldg(&Wg[row * 16 + q]);
        Wb[row * 68 + q * 4]     = u.x;
        Wb[row * 68 + q * 4 + 1] = u.y;
        Wb[row * 68 + q * 4 + 2] = u.z;
        Wb[row * 68 + q * 4 + 3] = u.w;
    }
    __syncthreads();
    if (tid < 64) {
        float s = 0.f, sq = 0.f;
        for (int c = 0; c < 128; c++) { float v = Yf[tid * 132 + c]; s += v; sq += v * v; }
        float m = s * (1.f / 128.f);
        float var = sq * (1.f / 128.f) - m * m;
        mr[tid] = m; mr[64 + tid] = rsqrtf(var + 1e-5f);
    }
    __syncthreads();
    for (int i = tid; i < 64 * 64; i += 256) {
        int p = i >> 6, q = i & 63;
        int k0 = q * 2;
        float f0 = (Yf[p * 132 + k0] - mr[p]) * mr[64 + p] * __ldg(&g2[k0]);
        float f1 = (Yf[p * 132 + k0 + 1] - mr[p]) * mr[64 + p] * __ldg(&g2[k0 + 1]);
        Yb[p * 68 + q] = pk(f0, f1);
    }
    __syncthreads();
    int wid = tid >> 5, lane = tid & 31;
    int wm = wid & 1, wn = wid >> 1;
    int gid = lane >> 2, tig = lane & 3;
    float c[2][4][4];
#pragma unroll
    for (int nt = 0; nt < 4; nt++) {
        int o = wn * 16 + (nt & 1) * 8 + (nt >> 1) * 64 + 2 * tig;
        float b0 = B4[o], b1 = B4[o + 1];
#pragma unroll
        for (int mt = 0; mt < 2; mt++) {
            c[mt][nt][0] = b0; c[mt][nt][1] = b1;
            c[mt][nt][2] = b0; c[mt][nt][3] = b1;
        }
    }
#pragma unroll
    for (int kw = 0; kw < 64; kw += 8) {
        uint32_t A[2][4];
#pragma unroll
        for (int mt = 0; mt < 2; mt++) {
            int r = wm * 32 + mt * 16 + gid;
            A[mt][0] = Yb[r * 68 + kw + tig];
            A[mt][1] = Yb[(r + 8) * 68 + kw + tig];
            A[mt][2] = Yb[r * 68 + kw + 4 + tig];
            A[mt][3] = Yb[(r + 8) * 68 + kw + 4 + tig];
        }
#pragma unroll
        for (int nt = 0; nt < 4; nt++) {
            int n = wn * 16 + (nt & 1) * 8 + (nt >> 1) * 64 + gid;
            uint32_t Bf[2];
            Bf[0] = Wb[n * 68 + kw + tig];
            Bf[1] = Wb[n * 68 + kw + 4 + tig];
#pragma unroll
            for (int mt = 0; mt < 2; mt++) mma_bf16(c[mt][nt], A[mt], Bf);
        }
    }
#pragma unroll
    for (int mt = 0; mt < 2; mt++) {
        size_t r0 = base + wm * 32 + mt * 16 + gid;
#pragma unroll
        for (int ntp = 0; ntp < 2; ntp++) {
            int o = wn * 16 + ntp * 8 + 2 * tig;
            *(float2*)&g_zg[r0 * 64 + o] =
                make_float2(c[mt][ntp][0] * c[mt][ntp + 2][0], c[mt][ntp][1] * c[mt][ntp + 2][1]);
            *(float2*)&g_zg[(r0 + 8) * 64 + o] =
                make_float2(c[mt][ntp][2] * c[mt][ntp + 2][2], c[mt][ntp][3] * c[mt][ntp + 2][3]);
        }
    }
}

// ------------------------- conv5 + final residuals, NCHW outputs -------------------------
__global__ void __launch_bounds__(256) k_c5out(const float* __restrict__ W5,
                                               const float* __restrict__ B5,
                                               const float* __restrict__ gamma,
                                               float* __restrict__ out) {
    extern __shared__ float sm[];
    float* Zs = sm;                    // 64*68
    float* W5s = sm + 64 * 68;         // 64*64
    float* Ys = W5s + 64 * 64;         // 64*132
    int tid = threadIdx.x;
    int base = blockIdx.x * 64;
    int b = base / HW;
    int pos = base - b * HW;
    for (int i = tid; i < 64 * 64; i += 256) {
        int p = i >> 6, k = i & 63;
        Zs[p * 68 + k] = g_zg[(size_t)(base + p) * 64 + k];
    }
    for (int i = tid; i < 64 * 64; i += 256) W5s[i] = W5[i];
    for (int i = tid; i < 64 * 128; i += 256) {
        int p = i >> 7, c = i & 127;
        Ys[p * 132 + c] = g_y[(size_t)(base + p) * 128 + c];
    }
    __syncthreads();
    int pr = tid & 15, og = tid >> 4;
    float acc[4][4];
#pragma unroll
    for (int j = 0; j < 4; j++) {
        float bv = B5[og * 4 + j];
#pragma unroll
        for (int i = 0; i < 4; i++) acc[i][j] = bv;
    }
#pragma unroll 4
    for (int k = 0; k < 64; k += 4) {
        float4 xv[4];
#pragma unroll
        for (int i = 0; i < 4; i++) xv[i] = *(const float4*)&Zs[(pr + 16 * i) * 68 + k];
#pragma unroll
        for (int j = 0; j < 4; j++) {
            float4 wv = *(const float4*)&W5s[(og * 4 + j) * 64 + k];
#pragma unroll
            for (int i = 0; i < 4; i++)
                acc[i][j] += xv[i].x * wv.x + xv[i].y * wv.y + xv[i].z * wv.z + xv[i].w * wv.w;
        }
    }
    const size_t HALF = (size_t)2 * 64 * HW;
#pragma unroll
    for (int i = 0; i < 4; i++) {
        int p = pr + 16 * i;
#pragma unroll
        for (int j = 0; j < 4; j++) {
            int cc = og * 4 + j;
            float z = acc[i][j] * __ldg(&gamma[cc]);
            size_t o = ((size_t)b * 64 + cc) * HW + pos + p;
            out[o] = Ys[p * 132 + cc] + z;
            out[HALF + o] = Ys[p * 132 + 64 + cc] + z;
        }
    }
}

// ------------------------- host -------------------------
extern "C" void kernel_launch(void* const* d_in, const int* in_sizes, int n_in,
                              void* d_out, int out_size) {
    const float* x_l     = (const float*)d_in[0];
    const float* x_r     = (const float*)d_in[1];
    const float* ln1_g   = (const float*)d_in[2];
    const float* pw1_w   = (const float*)d_in[3];
    const float* pw1_b   = (const float*)d_in[4];
    const float* val_w   = (const float*)d_in[5];
    const float* val_b   = (const float*)d_in[6];
    const float* dwc_w   = (const float*)d_in[7];
    const float* dwc_b   = (const float*)d_in[8];
    const float* om_w    = (const float*)d_in[9];
    const float* om_b    = (const float*)d_in[10];
    const float* outp_w  = (const float*)d_in[11];
    const float* outp_b  = (const float*)d_in[12];
    const float* sca_w   = (const float*)d_in[13];
    const float* sca_b   = (const float*)d_in[14];
    const float* conv3_w = (const float*)d_in[15];
    const float* conv3_b = (const float*)d_in[16];
    const float* norm2_g = (const float*)d_in[17];
    const float* conv4_w = (const float*)d_in[18];
    const float* conv4_b = (const float*)d_in[19];
    const float* conv5_w = (const float*)d_in[20];
    const float* conv5_b = (const float*)d_in[21];
    const float* beta    = (const float*)d_in[22];
    const float* gamma   = (const float*)d_in[23];
    float* out = (float*)d_out;

    const int SM_LNPW1V = (64 * 68 + 128 + 64 * 36 + 128 * 36 + 128 * 68 + 64 * 68) * 4; // 97792
    const int SM_TG     = (2 * 128 * 68) * 4;                                            // 69632
    const int SM_SOUT   = (128 * 68 + 64 * 68 + 8 * 112) * 4;                            // 55808
    const int SM_C3     = (64 * 132 + 64 * 128) * 4;
    const int SM_LN2    = (64 * 132 + 64 * 68 + 128 * 68 + 128) * 4;
    const int SM_C5     = (64 * 68 + 64 * 64 + 64 * 132) * 4;

    cudaFuncSetAttribute(k_lnpw1v,  cudaFuncAttributeMaxDynamicSharedMemorySize, SM_LNPW1V);
    cudaFuncSetAttribute(k_tgom,    cudaFuncAttributeMaxDynamicSharedMemorySize, SM_TG);
    cudaFuncSetAttribute(k_souter,  cudaFuncAttributeMaxDynamicSharedMemorySize, SM_SOUT);
    cudaFuncSetAttribute(k_conv3_y, cudaFuncAttributeMaxDynamicSharedMemorySize, SM_C3);
    cudaFuncSetAttribute(k_ln2c4,   cudaFuncAttributeMaxDynamicSharedMemorySize, SM_LN2);
    cudaFuncSetAttribute(k_c5out,   cudaFuncAttributeMaxDynamicSharedMemorySize, SM_C5);

    k_pack    <<<280, 256>>>(pw1_w, val_w, om_w, outp_w, conv4_w);
    k_lnpw1v  <<<P4 / 64, 256, SM_LNPW1V>>>(x_l, x_r, ln1_g, pw1_b, val_b);
    k_dwc4    <<<P4 * 128 / (256 * 4), 256>>>(dwc_w, dwc_b);
    k_tgom    <<<P4 / 128, 256, SM_TG>>>(om_b);
    k_souter  <<<P4 / 64, 256, SM_SOUT>>>(outp_b);
    k_pool    <<<64, 256>>>();
    k_sca     <<<1, 256>>>(sca_w, sca_b);
    k_conv3_y <<<P2 / 64, 256, SM_C3>>>(conv3_w, conv3_b, beta, x_l, x_r);
    k_ln2c4   <<<P2 / 64, 256, SM_LN2>>>(norm2_g, conv4_b);
    k_c5out   <<<P2 / 64, 256, SM_C5>>>(conv5_w, conv5_b, gamma, out);
}